// round 1
// baseline (speedup 1.0000x reference)
#include <cuda_runtime.h>
#include <cuda_bf16.h>
#include <math.h>

// Problem constants
#define B_   4
#define CIN  128
#define COUT 256
#define H_   128
#define W_   256
#define HW   (H_ * W_)          // 32768
#define KTOT (CIN * 9)          // 1152
#define K4   (KTOT / 4)         // 288
#define TILE_P 16               // pixels per block

// Scratch (static device arrays; no allocation allowed)
__device__ float  g_xT[(size_t)B_ * HW * CIN];   // 64 MB: x transposed to (B, HW, Cin)
__device__ float4 g_Wt[K4 * COUT];               // 1.18 MB: weights as [k4][co] float4(k..k+3)

// ---------------------------------------------------------------------------
// Kernel 1: transpose x (B, Cin, H, W) -> g_xT (B, HW, Cin)
// ---------------------------------------------------------------------------
__global__ void transpose_x_kernel(const float* __restrict__ x) {
    __shared__ float tile[32][33];
    const int b    = blockIdx.z;
    const int cin0 = blockIdx.y * 32;
    const int p0   = blockIdx.x * 32;
    const int tx = threadIdx.x, ty = threadIdx.y;
    tile[ty][tx] = x[((size_t)b * CIN + (cin0 + ty)) * HW + (p0 + tx)];
    __syncthreads();
    g_xT[((size_t)b * HW + (p0 + ty)) * CIN + (cin0 + tx)] = tile[tx][ty];
}

// ---------------------------------------------------------------------------
// Kernel 2: weight prep. weight (Cout, Cin, 3, 3) -> g_Wt[k4*256+co] = 4
// consecutive k values, where k = tap*128 + cin, tap = r*3+c.
// ---------------------------------------------------------------------------
__global__ void weight_prep_kernel(const float* __restrict__ wsrc) {
    const int j  = blockIdx.x * 256 + threadIdx.x;   // 0 .. K4*COUT-1
    const int k4 = j >> 8;
    const int co = j & 255;
    float4 v;
    int k;
    k = k4 * 4 + 0; v.x = wsrc[(co * CIN + (k & 127)) * 9 + (k >> 7)];
    k = k4 * 4 + 1; v.y = wsrc[(co * CIN + (k & 127)) * 9 + (k >> 7)];
    k = k4 * 4 + 2; v.z = wsrc[(co * CIN + (k & 127)) * 9 + (k >> 7)];
    k = k4 * 4 + 3; v.w = wsrc[(co * CIN + (k & 127)) * 9 + (k >> 7)];
    g_Wt[j] = v;
}

// ---------------------------------------------------------------------------
// Kernel 3: main fused gather + implicit GEMM.
// Block: 256 threads (one per Cout), TILE_P=16 consecutive pixels (same row).
// Phase 1: 8 warps gather+bilinear 16px x 9 taps x 128 cin into smem s[pp][k].
// Phase 2: each thread (one co) accumulates 16 pixels over K=1152.
// ---------------------------------------------------------------------------
extern __shared__ float s_smem[];   // [TILE_P][KTOT] = 16*1152 floats = 73728 B

__global__ __launch_bounds__(256, 2)
void sphere_conv_main_kernel(const float* __restrict__ grid,
                             const float* __restrict__ bias,
                             float* __restrict__ out) {
    const int b  = blockIdx.y;
    const int p0 = blockIdx.x * TILE_P;
    const int tid  = threadIdx.x;
    const int lane = tid & 31;
    const int warp = tid >> 5;   // 0..7

    // ---- Phase 1: gather / bilinear sample into smem ----
    const float4* __restrict__ xb =
        (const float4*)(g_xT + (size_t)b * HW * CIN);

    for (int job = warp; job < TILE_P * 9; job += 8) {
        const int pp  = job / 9;
        const int tap = job - pp * 9;
        const int p = p0 + pp;
        const int h = p >> 8;          // W_=256
        const int w = p & 255;
        const int r = tap / 3;
        const int c = tap - r * 3;

        const int gi = (h * 3 + r) * (W_ * 3) + (w * 3 + c);
        const float gx = grid[2 * gi + 0];
        const float gy = grid[2 * gi + 1];

        const float ix = ((gx + 1.0f) * (float)W_ - 1.0f) * 0.5f;
        const float iy = ((gy + 1.0f) * (float)H_ - 1.0f) * 0.5f;
        const float x0f = floorf(ix), y0f = floorf(iy);
        const float fx = ix - x0f,   fy = iy - y0f;
        const int xx0 = (int)x0f, yy0 = (int)y0f;
        const int xx1 = xx0 + 1,  yy1 = yy0 + 1;

        float w00 = (1.0f - fx) * (1.0f - fy);
        float w10 = fx * (1.0f - fy);
        float w01 = (1.0f - fx) * fy;
        float w11 = fx * fy;
        if (xx0 < 0 || xx0 >= W_) { w00 = 0.0f; w01 = 0.0f; }
        if (xx1 < 0 || xx1 >= W_) { w10 = 0.0f; w11 = 0.0f; }
        if (yy0 < 0 || yy0 >= H_) { w00 = 0.0f; w10 = 0.0f; }
        if (yy1 < 0 || yy1 >= H_) { w01 = 0.0f; w11 = 0.0f; }

        const int xi0 = min(max(xx0, 0), W_ - 1);
        const int xi1 = min(max(xx1, 0), W_ - 1);
        const int yi0 = min(max(yy0, 0), H_ - 1);
        const int yi1 = min(max(yy1, 0), H_ - 1);

        const int p00 = yi0 * W_ + xi0;
        const int p10 = yi0 * W_ + xi1;
        const int p01 = yi1 * W_ + xi0;
        const int p11 = yi1 * W_ + xi1;

        // each lane: one float4 of channels (CIN=128 = 32 lanes * 4)
        const float4 v00 = xb[(size_t)p00 * 32 + lane];
        const float4 v10 = xb[(size_t)p10 * 32 + lane];
        const float4 v01 = xb[(size_t)p01 * 32 + lane];
        const float4 v11 = xb[(size_t)p11 * 32 + lane];

        float4 sv;
        sv.x = w00 * v00.x + w10 * v10.x + w01 * v01.x + w11 * v11.x;
        sv.y = w00 * v00.y + w10 * v10.y + w01 * v01.y + w11 * v11.y;
        sv.z = w00 * v00.z + w10 * v10.z + w01 * v01.z + w11 * v11.z;
        sv.w = w00 * v00.w + w10 * v10.w + w01 * v01.w + w11 * v11.w;

        ((float4*)(s_smem + pp * KTOT + tap * CIN))[lane] = sv;
    }
    __syncthreads();

    // ---- Phase 2: per-thread (one co) GEMM over K=1152, 16 pixels ----
    const int co = tid;
    float acc[TILE_P];
#pragma unroll
    for (int pp = 0; pp < TILE_P; ++pp) acc[pp] = 0.0f;

    const float4* __restrict__ wt = g_Wt + co;

#pragma unroll 2
    for (int k4 = 0; k4 < K4; ++k4) {
        const float4 wv = wt[(size_t)k4 * COUT];
#pragma unroll
        for (int pp = 0; pp < TILE_P; ++pp) {
            const float4 sv = *(const float4*)(s_smem + pp * KTOT + k4 * 4);
            float a = acc[pp];
            a = fmaf(wv.x, sv.x, a);
            a = fmaf(wv.y, sv.y, a);
            a = fmaf(wv.z, sv.z, a);
            a = fmaf(wv.w, sv.w, a);
            acc[pp] = a;
        }
    }

    const float bv = bias[co];
    float* op = out + ((size_t)b * COUT + co) * HW + p0;
    float4* o4 = (float4*)op;
#pragma unroll
    for (int i = 0; i < TILE_P / 4; ++i) {
        o4[i] = make_float4(acc[4 * i + 0] + bv, acc[4 * i + 1] + bv,
                            acc[4 * i + 2] + bv, acc[4 * i + 3] + bv);
    }
}

// ---------------------------------------------------------------------------
extern "C" void kernel_launch(void* const* d_in, const int* in_sizes, int n_in,
                              void* d_out, int out_size) {
    const float* x      = (const float*)d_in[0];   // (4,128,128,256)
    const float* weight = (const float*)d_in[1];   // (256,128,3,3)
    const float* bias   = (const float*)d_in[2];   // (256,)
    const float* grid   = (const float*)d_in[3];   // (1,384,768,2)
    float* out = (float*)d_out;                    // (4,256,128,256)

    static bool attr_set = false;
    if (!attr_set) {
        cudaFuncSetAttribute(sphere_conv_main_kernel,
                             cudaFuncAttributeMaxDynamicSharedMemorySize,
                             TILE_P * KTOT * (int)sizeof(float));
        attr_set = true;
    }

    // 1) transpose x -> (B, HW, Cin)
    {
        dim3 g(HW / 32, CIN / 32, B_);
        dim3 blk(32, 32);
        transpose_x_kernel<<<g, blk>>>(x);
    }
    // 2) weight prep -> [k4][co] float4
    weight_prep_kernel<<<K4, 256>>>(weight);
    // 3) main fused kernel
    {
        dim3 g(HW / TILE_P, B_);
        sphere_conv_main_kernel<<<g, 256, TILE_P * KTOT * sizeof(float)>>>(
            grid, bias, out);
    }
}

// round 3
// speedup vs baseline: 2.0078x; 2.0078x over previous
#include <cuda_runtime.h>
#include <cuda_bf16.h>
#include <cstdint>
#include <math.h>

// ---------------- problem constants ----------------
#define B_   4
#define CIN  128
#define COUT 256
#define H_   128
#define W_   256
#define HW   (H_ * W_)              // 32768
#define TILE_M 128                  // pixels per CTA
#define NTILES (B_ * HW / TILE_M)   // 1024

// ---------------- device scratch ----------------
__device__ float g_xT[(size_t)B_ * HW * CIN];        // 64 MB (B, HW, Cin)
__device__ unsigned char g_Whi[9 * 65536];           // per tap: 256 co x 256B (128 bf16), swizzled
__device__ unsigned char g_Wlo[9 * 65536];

// ---------------- smem layout (1024-aligned base) ----------------
#define SM_AHI  0            // 128 rows x 256B = 32KB
#define SM_ALO  32768        // 32KB
#define SM_WHI  65536        // 256 rows x 256B = 64KB
#define SM_WLO  131072       // 64KB
#define SM_BIAS 196608       // 1KB
#define SM_TOTAL (197632 + 1024)
// epilogue reuses [0, 128KB) as Dsm[co][px] fp32

// byte-in-row swizzle for 256B rows (8-row period, 16B granules)
__device__ __forceinline__ uint32_t bswz(uint32_t row, uint32_t col) {
    return col ^ ((row & 7u) << 4);
}

__device__ __forceinline__ uint32_t smem_u32(const void* p) {
    uint32_t a;
    asm("{ .reg .u64 t; cvta.to.shared.u64 t, %1; cvt.u32.u64 %0, t; }" : "=r"(a) : "l"(p));
    return a;
}

__device__ __forceinline__ void ldm_x4(uint32_t& r0, uint32_t& r1, uint32_t& r2, uint32_t& r3,
                                       uint32_t addr) {
    asm volatile("ldmatrix.sync.aligned.m8n8.x4.shared.b16 {%0,%1,%2,%3}, [%4];"
                 : "=r"(r0), "=r"(r1), "=r"(r2), "=r"(r3) : "r"(addr));
}

__device__ __forceinline__ void mma_16816(float& c0, float& c1, float& c2, float& c3,
                                          uint32_t a0, uint32_t a1, uint32_t a2, uint32_t a3,
                                          uint32_t b0, uint32_t b1) {
    asm volatile(
        "mma.sync.aligned.m16n8k16.row.col.f32.bf16.bf16.f32 "
        "{%0,%1,%2,%3}, {%4,%5,%6,%7}, {%8,%9}, {%0,%1,%2,%3};"
        : "+f"(c0), "+f"(c1), "+f"(c2), "+f"(c3)
        : "r"(a0), "r"(a1), "r"(a2), "r"(a3), "r"(b0), "r"(b1));
}

// ---------------------------------------------------------------------------
// Kernel 1: transpose x (B, Cin, H, W) -> g_xT (B, HW, Cin)
// ---------------------------------------------------------------------------
__global__ void transpose_x_kernel(const float* __restrict__ x) {
    __shared__ float tile[32][33];
    const int b    = blockIdx.z;
    const int cin0 = blockIdx.y * 32;
    const int p0   = blockIdx.x * 32;
    const int tx = threadIdx.x, ty = threadIdx.y;
    tile[ty][tx] = x[((size_t)b * CIN + (cin0 + ty)) * HW + (p0 + tx)];
    __syncthreads();
    g_xT[((size_t)b * HW + (p0 + ty)) * CIN + (cin0 + tx)] = tile[tx][ty];
}

// ---------------------------------------------------------------------------
// Kernel 2: weight prep. weight (Cout, Cin, 3, 3) -> bf16 hi/lo per tap,
// 256 co rows x 128 bf16 (256B), swizzled with bswz.
// ---------------------------------------------------------------------------
__global__ void weight_prep_bf16_kernel(const float* __restrict__ wsrc) {
    const int idx = blockIdx.x * 256 + threadIdx.x;   // < 9*256*128 = 294912
    if (idx >= 9 * 256 * 128) return;
    const int cin = idx & 127;
    const int co  = (idx >> 7) & 255;
    const int t   = idx >> 15;
    const float v = wsrc[(co * CIN + cin) * 9 + t];
    const __nv_bfloat16 hi = __float2bfloat16(v);
    const __nv_bfloat16 lo = __float2bfloat16(v - __bfloat162float(hi));
    const uint32_t off = (uint32_t)co * 256 + bswz(co, (uint32_t)cin * 2);
    *(__nv_bfloat16*)(g_Whi + (size_t)t * 65536 + off) = hi;
    *(__nv_bfloat16*)(g_Wlo + (size_t)t * 65536 + off) = lo;
}

// ---------------------------------------------------------------------------
// Kernel 3: gather + bf16-split + ldmatrix/mma.sync implicit GEMM.
// 256 threads = 8 warps, warp grid 2(M) x 4(N), warp tile 64x64, fp32 acc.
// Per tap: stage W hi/lo (128KB), gather+split A (128px x 128ch), then
// 3 passes x 8 k-steps of mma. Epilogue via smem transpose.
// ---------------------------------------------------------------------------
__global__ __launch_bounds__(256, 1)
void sphere_hmma_kernel(const float* __restrict__ gridp,
                        const float* __restrict__ bias,
                        float* __restrict__ out) {
    extern __shared__ char dsm[];
    const uint32_t raw = smem_u32(dsm);
    const uint32_t sb  = (raw + 1023u) & ~1023u;
    char* const smp = dsm + (sb - raw);

    const int tid  = threadIdx.x;
    const int lane = tid & 31;
    const int warp = tid >> 5;
    const int warp_m = warp >> 2;       // 0..1
    const int warp_n = warp & 3;        // 0..3
    const int tile = blockIdx.x;
    const int b    = tile >> 8;
    const int p0   = (tile & 255) * TILE_M;

    if (tid < 256) ((float*)(smp + SM_BIAS))[tid] = bias[tid];

    const float4* __restrict__ xb = (const float4*)(g_xT + (size_t)b * HW * CIN);

    float acc[4][8][4];
#pragma unroll
    for (int mi = 0; mi < 4; ++mi)
#pragma unroll
        for (int ni = 0; ni < 8; ++ni)
#pragma unroll
            for (int q = 0; q < 4; ++q) acc[mi][ni][q] = 0.0f;

    // precomputed ldmatrix lane addresses (offsets within buffers)
    // A: row = m0 + (lane & 15), kbyte = k0*2 + (lane>>4)*16
    const uint32_t a_row_in_warp = (uint32_t)(lane & 15);
    const uint32_t a_koff        = (uint32_t)((lane >> 4) << 4);
    // B: n = nbase + ((lane>>4)&1)*8 + (lane&7), kbyte = k0*2 + ((lane>>3)&1)*16
    const uint32_t b_n_in_pair   = (uint32_t)(((lane >> 4) & 1) * 8 + (lane & 7));
    const uint32_t b_koff        = (uint32_t)(((lane >> 3) & 1) << 4);

    for (int t = 0; t < 9; ++t) {
        __syncthreads();   // previous tap's MMA reads done before overwrite

        // ---- stage W hi/lo (pre-swizzled, linear 64KB copies each) ----
        {
            const float4* __restrict__ srcH = (const float4*)(g_Whi + (size_t)t * 65536);
            const float4* __restrict__ srcL = (const float4*)(g_Wlo + (size_t)t * 65536);
            float4* dstH = (float4*)(smp + SM_WHI);
            float4* dstL = (float4*)(smp + SM_WLO);
#pragma unroll
            for (int i = 0; i < 16; ++i) {
                dstH[tid + 256 * i] = srcH[tid + 256 * i];
                dstL[tid + 256 * i] = srcL[tid + 256 * i];
            }
        }

        // ---- gather + bilinear + bf16 split into A hi/lo ----
        const int r = t / 3;
        const int c = t - r * 3;
#pragma unroll 1
        for (int pp = warp; pp < TILE_M; pp += 8) {
            const int p = p0 + pp;
            const int h = p >> 8;
            const int w = p & 255;

            const int gi = (h * 3 + r) * (W_ * 3) + (w * 3 + c);
            const float gx = gridp[2 * gi + 0];
            const float gy = gridp[2 * gi + 1];

            const float ix = ((gx + 1.0f) * (float)W_ - 1.0f) * 0.5f;
            const float iy = ((gy + 1.0f) * (float)H_ - 1.0f) * 0.5f;
            const float x0f = floorf(ix), y0f = floorf(iy);
            const float fx = ix - x0f, fy = iy - y0f;
            const int xx0 = (int)x0f, yy0 = (int)y0f;
            const int xx1 = xx0 + 1, yy1 = yy0 + 1;

            float w00 = (1.0f - fx) * (1.0f - fy);
            float w10 = fx * (1.0f - fy);
            float w01 = (1.0f - fx) * fy;
            float w11 = fx * fy;
            if (xx0 < 0 || xx0 >= W_) { w00 = 0.0f; w01 = 0.0f; }
            if (xx1 < 0 || xx1 >= W_) { w10 = 0.0f; w11 = 0.0f; }
            if (yy0 < 0 || yy0 >= H_) { w00 = 0.0f; w10 = 0.0f; }
            if (yy1 < 0 || yy1 >= H_) { w01 = 0.0f; w11 = 0.0f; }

            const int xi0 = min(max(xx0, 0), W_ - 1);
            const int xi1 = min(max(xx1, 0), W_ - 1);
            const int yi0 = min(max(yy0, 0), H_ - 1);
            const int yi1 = min(max(yy1, 0), H_ - 1);

            const float4 v00 = xb[(size_t)(yi0 * W_ + xi0) * 32 + lane];
            const float4 v10 = xb[(size_t)(yi0 * W_ + xi1) * 32 + lane];
            const float4 v01 = xb[(size_t)(yi1 * W_ + xi0) * 32 + lane];
            const float4 v11 = xb[(size_t)(yi1 * W_ + xi1) * 32 + lane];

            float4 sv;
            sv.x = w00 * v00.x + w10 * v10.x + w01 * v01.x + w11 * v11.x;
            sv.y = w00 * v00.y + w10 * v10.y + w01 * v01.y + w11 * v11.y;
            sv.z = w00 * v00.z + w10 * v10.z + w01 * v01.z + w11 * v11.z;
            sv.w = w00 * v00.w + w10 * v10.w + w01 * v01.w + w11 * v11.w;

            const __nv_bfloat16 hx = __float2bfloat16(sv.x);
            const __nv_bfloat16 hy = __float2bfloat16(sv.y);
            const __nv_bfloat16 hz = __float2bfloat16(sv.z);
            const __nv_bfloat16 hw2 = __float2bfloat16(sv.w);
            const __nv_bfloat16 lx = __float2bfloat16(sv.x - __bfloat162float(hx));
            const __nv_bfloat16 ly = __float2bfloat16(sv.y - __bfloat162float(hy));
            const __nv_bfloat16 lz = __float2bfloat16(sv.z - __bfloat162float(hz));
            const __nv_bfloat16 lw = __float2bfloat16(sv.w - __bfloat162float(hw2));

            const uint32_t hi01 = (uint32_t)__bfloat16_as_ushort(hx) |
                                  ((uint32_t)__bfloat16_as_ushort(hy) << 16);
            const uint32_t hi23 = (uint32_t)__bfloat16_as_ushort(hz) |
                                  ((uint32_t)__bfloat16_as_ushort(hw2) << 16);
            const uint32_t lo01 = (uint32_t)__bfloat16_as_ushort(lx) |
                                  ((uint32_t)__bfloat16_as_ushort(ly) << 16);
            const uint32_t lo23 = (uint32_t)__bfloat16_as_ushort(lz) |
                                  ((uint32_t)__bfloat16_as_ushort(lw) << 16);

            const uint32_t off = (uint32_t)pp * 256 + bswz((uint32_t)pp, (uint32_t)lane * 8);
            *(uint2*)(smp + SM_AHI + off) = make_uint2(hi01, hi23);
            *(uint2*)(smp + SM_ALO + off) = make_uint2(lo01, lo23);
        }

        __syncthreads();

        // ---- 3 passes x 8 k-steps of mma ----
#pragma unroll
        for (int ps = 0; ps < 3; ++ps) {
            const uint32_t Abase = sb + ((ps == 1) ? SM_ALO : SM_AHI);
            const uint32_t Wbase = sb + ((ps == 2) ? SM_WLO : SM_WHI);
#pragma unroll
            for (int k0 = 0; k0 < 8; ++k0) {
                const uint32_t kb = (uint32_t)k0 * 32;   // k0*16 elems * 2B

                // B fragments: 8 n-tiles via 4 ldmatrix.x4
                uint32_t bfr[8][2];
#pragma unroll
                for (int np = 0; np < 4; ++np) {
                    const uint32_t n = (uint32_t)(warp_n * 64 + np * 16) + b_n_in_pair;
                    const uint32_t addr = Wbase + n * 256 + bswz(n, kb + b_koff);
                    ldm_x4(bfr[np * 2][0], bfr[np * 2][1],
                           bfr[np * 2 + 1][0], bfr[np * 2 + 1][1], addr);
                }

                // A fragments + MMAs
#pragma unroll
                for (int mi = 0; mi < 4; ++mi) {
                    const uint32_t row = (uint32_t)(warp_m * 64 + mi * 16) + a_row_in_warp;
                    const uint32_t addr = Abase + row * 256 + bswz(row, kb + a_koff);
                    uint32_t a0, a1, a2, a3;
                    ldm_x4(a0, a1, a2, a3, addr);
#pragma unroll
                    for (int ni = 0; ni < 8; ++ni) {
                        mma_16816(acc[mi][ni][0], acc[mi][ni][1],
                                  acc[mi][ni][2], acc[mi][ni][3],
                                  a0, a1, a2, a3, bfr[ni][0], bfr[ni][1]);
                    }
                }
            }
        }
    }

    // ---- epilogue: acc -> Dsm[co][px] -> coalesced out ----
    __syncthreads();
    float* Dsm = (float*)smp;   // 256 x 128 fp32 = 128KB (reuses A/W)
    {
        const int rbase = warp_m * 64 + (lane >> 2);
        const int cbase = warp_n * 64 + 2 * (lane & 3);
#pragma unroll
        for (int mi = 0; mi < 4; ++mi) {
#pragma unroll
            for (int ni = 0; ni < 8; ++ni) {
                const int rr = rbase + mi * 16;
                const int cc = cbase + ni * 8;
                Dsm[(cc    ) * 128 + rr    ] = acc[mi][ni][0];
                Dsm[(cc + 1) * 128 + rr    ] = acc[mi][ni][1];
                Dsm[(cc    ) * 128 + rr + 8] = acc[mi][ni][2];
                Dsm[(cc + 1) * 128 + rr + 8] = acc[mi][ni][3];
            }
        }
    }
    __syncthreads();

    {
        const float* bs = (const float*)(smp + SM_BIAS);
        float* ob = out + (size_t)b * COUT * HW + p0;
#pragma unroll 4
        for (int it = 0; it < 32; ++it) {
            const int co = it * 8 + warp;
            const float bv = bs[co];
            float4 v = ((const float4*)(Dsm + co * 128))[lane];
            v.x += bv; v.y += bv; v.z += bv; v.w += bv;
            ((float4*)(ob + (size_t)co * HW))[lane] = v;
        }
    }
}

// ---------------------------------------------------------------------------
extern "C" void kernel_launch(void* const* d_in, const int* in_sizes, int n_in,
                              void* d_out, int out_size) {
    const float* x      = (const float*)d_in[0];   // (4,128,128,256)
    const float* weight = (const float*)d_in[1];   // (256,128,3,3)
    const float* bias   = (const float*)d_in[2];   // (256,)
    const float* grid   = (const float*)d_in[3];   // (1,384,768,2)
    float* out = (float*)d_out;                    // (4,256,128,256)

    cudaFuncSetAttribute(sphere_hmma_kernel,
                         cudaFuncAttributeMaxDynamicSharedMemorySize, SM_TOTAL);

    {
        dim3 g(HW / 32, CIN / 32, B_);
        dim3 blk(32, 32);
        transpose_x_kernel<<<g, blk>>>(x);
    }
    weight_prep_bf16_kernel<<<(9 * 256 * 128 + 255) / 256, 256>>>(weight);
    sphere_hmma_kernel<<<NTILES, 256, SM_TOTAL>>>(grid, bias, out);
}

// round 4
// speedup vs baseline: 3.0639x; 1.5260x over previous
#include <cuda_runtime.h>
#include <cuda_fp16.h>
#include <cstdint>
#include <math.h>

// ---------------- problem constants ----------------
#define B_   4
#define CIN  128
#define COUT 256
#define H_   128
#define W_   256
#define HW   (H_ * W_)              // 32768
#define TILE_M 128                  // pixels per CTA
#define NTILES (B_ * HW / TILE_M)   // 1024

// ---------------- device scratch ----------------
__device__ float g_xT[(size_t)B_ * HW * CIN];        // 64 MB (B, HW, Cin)
__device__ unsigned char g_Whi[9 * 65536];           // per tap: 256 co x 256B (128 fp16), swizzled
__device__ unsigned char g_Wlo[9 * 65536];

// ---------------- smem layout (1024-aligned base) ----------------
#define SM_A0   0            // 128 rows x 256B = 32KB (fp16 A, buffer 0)
#define SM_A1   32768        // 32KB (buffer 1)
#define SM_WHI  65536        // 64KB
#define SM_WLO  131072       // 64KB
#define SM_BIAS 196608       // 1KB
#define SM_TOTAL (197632 + 1024)
// epilogue reuses [0, 128KB) as Dsm[co][px] fp32

// byte-in-row swizzle for 256B rows (8-row period, 16B granules)
__device__ __forceinline__ uint32_t bswz(uint32_t row, uint32_t col) {
    return col ^ ((row & 7u) << 4);
}

__device__ __forceinline__ uint32_t smem_u32(const void* p) {
    uint32_t a;
    asm("{ .reg .u64 t; cvta.to.shared.u64 t, %1; cvt.u32.u64 %0, t; }" : "=r"(a) : "l"(p));
    return a;
}

__device__ __forceinline__ void ldm_x4(uint32_t& r0, uint32_t& r1, uint32_t& r2, uint32_t& r3,
                                       uint32_t addr) {
    asm volatile("ldmatrix.sync.aligned.m8n8.x4.shared.b16 {%0,%1,%2,%3}, [%4];"
                 : "=r"(r0), "=r"(r1), "=r"(r2), "=r"(r3) : "r"(addr));
}

__device__ __forceinline__ void mma_16816(float& c0, float& c1, float& c2, float& c3,
                                          uint32_t a0, uint32_t a1, uint32_t a2, uint32_t a3,
                                          uint32_t b0, uint32_t b1) {
    asm volatile(
        "mma.sync.aligned.m16n8k16.row.col.f32.f16.f16.f32 "
        "{%0,%1,%2,%3}, {%4,%5,%6,%7}, {%8,%9}, {%0,%1,%2,%3};"
        : "+f"(c0), "+f"(c1), "+f"(c2), "+f"(c3)
        : "r"(a0), "r"(a1), "r"(a2), "r"(a3), "r"(b0), "r"(b1));
}

__device__ __forceinline__ void cp_async16(uint32_t dst, const void* src) {
    asm volatile("cp.async.cg.shared.global [%0], [%1], 16;" :: "r"(dst), "l"(src) : "memory");
}
__device__ __forceinline__ void cp_commit() {
    asm volatile("cp.async.commit_group;" ::: "memory");
}
__device__ __forceinline__ void cp_wait0() {
    asm volatile("cp.async.wait_group 0;" ::: "memory");
}

// stage a 64KB pre-swizzled W block (gmem linear -> smem linear), non-blocking
__device__ __forceinline__ void stageW_async(uint32_t smem_dst, const unsigned char* src, int tid) {
#pragma unroll
    for (int i = 0; i < 16; ++i) {
        cp_async16(smem_dst + i * 4096 + tid * 16, src + i * 4096 + tid * 16);
    }
}

// ---------------------------------------------------------------------------
// Kernel 1: transpose x (B, Cin, H, W) -> g_xT (B, HW, Cin)
// ---------------------------------------------------------------------------
__global__ void transpose_x_kernel(const float* __restrict__ x) {
    __shared__ float tile[32][33];
    const int b    = blockIdx.z;
    const int cin0 = blockIdx.y * 32;
    const int p0   = blockIdx.x * 32;
    const int tx = threadIdx.x, ty = threadIdx.y;   // 32 x 8
#pragma unroll
    for (int j = 0; j < 4; ++j)
        tile[ty + 8 * j][tx] = x[((size_t)b * CIN + (cin0 + ty + 8 * j)) * HW + (p0 + tx)];
    __syncthreads();
#pragma unroll
    for (int j = 0; j < 4; ++j)
        g_xT[((size_t)b * HW + (p0 + ty + 8 * j)) * CIN + (cin0 + tx)] = tile[tx][ty + 8 * j];
}

// ---------------------------------------------------------------------------
// Kernel 2: weight prep. weight (Cout, Cin, 3, 3) -> fp16 hi/lo per tap,
// 256 co rows x 128 fp16 (256B), swizzled with bswz.
// ---------------------------------------------------------------------------
__global__ void weight_prep_f16_kernel(const float* __restrict__ wsrc) {
    const int idx = blockIdx.x * 256 + threadIdx.x;   // < 9*256*128 = 294912
    if (idx >= 9 * 256 * 128) return;
    const int cin = idx & 127;
    const int co  = (idx >> 7) & 255;
    const int t   = idx >> 15;
    const float v = wsrc[(co * CIN + cin) * 9 + t];
    const __half hi = __float2half(v);
    const __half lo = __float2half(v - __half2float(hi));
    const uint32_t off = (uint32_t)co * 256 + bswz(co, (uint32_t)cin * 2);
    *(__half*)(g_Whi + (size_t)t * 65536 + off) = hi;
    *(__half*)(g_Wlo + (size_t)t * 65536 + off) = lo;
}

// ---------------------------------------------------------------------------
// gather one half-tile (64 px) of tap `tap` into A buffer (fp16, swizzled)
// ---------------------------------------------------------------------------
__device__ __forceinline__ void gather_half(const float* __restrict__ gridp,
                                            const float4* __restrict__ xb,
                                            char* abuf, int p0, int tap, int half,
                                            int lane, int warp) {
    const int r = tap / 3;
    const int c = tap - r * 3;
#pragma unroll 1
    for (int i = 0; i < 8; ++i) {
        const int pp = half * 64 + i * 8 + warp;
        const int p = p0 + pp;
        const int h = p >> 8;
        const int w = p & 255;

        const int gi = (h * 3 + r) * (W_ * 3) + (w * 3 + c);
        const float gx = gridp[2 * gi + 0];
        const float gy = gridp[2 * gi + 1];

        const float ix = ((gx + 1.0f) * (float)W_ - 1.0f) * 0.5f;
        const float iy = ((gy + 1.0f) * (float)H_ - 1.0f) * 0.5f;
        const float x0f = floorf(ix), y0f = floorf(iy);
        const float fx = ix - x0f, fy = iy - y0f;
        const int xx0 = (int)x0f, yy0 = (int)y0f;
        const int xx1 = xx0 + 1, yy1 = yy0 + 1;

        float w00 = (1.0f - fx) * (1.0f - fy);
        float w10 = fx * (1.0f - fy);
        float w01 = (1.0f - fx) * fy;
        float w11 = fx * fy;
        if (xx0 < 0 || xx0 >= W_) { w00 = 0.0f; w01 = 0.0f; }
        if (xx1 < 0 || xx1 >= W_) { w10 = 0.0f; w11 = 0.0f; }
        if (yy0 < 0 || yy0 >= H_) { w00 = 0.0f; w10 = 0.0f; }
        if (yy1 < 0 || yy1 >= H_) { w01 = 0.0f; w11 = 0.0f; }

        const int xi0 = min(max(xx0, 0), W_ - 1);
        const int xi1 = min(max(xx1, 0), W_ - 1);
        const int yi0 = min(max(yy0, 0), H_ - 1);
        const int yi1 = min(max(yy1, 0), H_ - 1);

        const float4 v00 = xb[(size_t)(yi0 * W_ + xi0) * 32 + lane];
        const float4 v10 = xb[(size_t)(yi0 * W_ + xi1) * 32 + lane];
        const float4 v01 = xb[(size_t)(yi1 * W_ + xi0) * 32 + lane];
        const float4 v11 = xb[(size_t)(yi1 * W_ + xi1) * 32 + lane];

        float4 sv;
        sv.x = w00 * v00.x + w10 * v10.x + w01 * v01.x + w11 * v11.x;
        sv.y = w00 * v00.y + w10 * v10.y + w01 * v01.y + w11 * v11.y;
        sv.z = w00 * v00.z + w10 * v10.z + w01 * v01.z + w11 * v11.z;
        sv.w = w00 * v00.w + w10 * v10.w + w01 * v01.w + w11 * v11.w;

        const __half hx = __float2half(sv.x);
        const __half hy = __float2half(sv.y);
        const __half hz = __float2half(sv.z);
        const __half hw2 = __float2half(sv.w);

        const uint32_t h01 = (uint32_t)__half_as_ushort(hx) |
                             ((uint32_t)__half_as_ushort(hy) << 16);
        const uint32_t h23 = (uint32_t)__half_as_ushort(hz) |
                             ((uint32_t)__half_as_ushort(hw2) << 16);

        const uint32_t off = (uint32_t)pp * 256 + bswz((uint32_t)pp, (uint32_t)lane * 8);
        *(uint2*)(abuf + off) = make_uint2(h01, h23);
    }
}

// ---------------------------------------------------------------------------
// one MMA pass: A[128x128] x W[256x128]^T, K=128 (8 ksteps), warp tile 64x64
// ---------------------------------------------------------------------------
__device__ __forceinline__ void mma_pass(uint32_t Abase, uint32_t Wbase,
                                         float (*acc)[8][4],
                                         uint32_t a_row_in_warp, uint32_t a_koff,
                                         uint32_t b_n_in_pair, uint32_t b_koff,
                                         int warp_m, int warp_n) {
#pragma unroll
    for (int k0 = 0; k0 < 8; ++k0) {
        const uint32_t kb = (uint32_t)k0 * 32;

        uint32_t bfr[8][2];
#pragma unroll
        for (int np = 0; np < 4; ++np) {
            const uint32_t n = (uint32_t)(warp_n * 64 + np * 16) + b_n_in_pair;
            const uint32_t addr = Wbase + n * 256 + bswz(n, kb + b_koff);
            ldm_x4(bfr[np * 2][0], bfr[np * 2][1],
                   bfr[np * 2 + 1][0], bfr[np * 2 + 1][1], addr);
        }

#pragma unroll
        for (int mi = 0; mi < 4; ++mi) {
            const uint32_t row = (uint32_t)(warp_m * 64 + mi * 16) + a_row_in_warp;
            const uint32_t addr = Abase + row * 256 + bswz(row, kb + a_koff);
            uint32_t a0, a1, a2, a3;
            ldm_x4(a0, a1, a2, a3, addr);
#pragma unroll
            for (int ni = 0; ni < 8; ++ni) {
                mma_16816(acc[mi][ni][0], acc[mi][ni][1],
                          acc[mi][ni][2], acc[mi][ni][3],
                          a0, a1, a2, a3, bfr[ni][0], bfr[ni][1]);
            }
        }
    }
}

// ---------------------------------------------------------------------------
// Kernel 3: pipelined gather + fp16 2-pass ldmatrix/mma implicit GEMM.
// ---------------------------------------------------------------------------
__global__ __launch_bounds__(256, 1)
void sphere_hmma_kernel(const float* __restrict__ gridp,
                        const float* __restrict__ bias,
                        float* __restrict__ out) {
    extern __shared__ char dsm[];
    const uint32_t raw = smem_u32(dsm);
    const uint32_t sb  = (raw + 1023u) & ~1023u;
    char* const smp = dsm + (sb - raw);

    const int tid  = threadIdx.x;
    const int lane = tid & 31;
    const int warp = tid >> 5;
    const int warp_m = warp >> 2;       // 0..1
    const int warp_n = warp & 3;        // 0..3
    const int tile = blockIdx.x;
    const int b    = tile >> 8;
    const int p0   = (tile & 255) * TILE_M;

    ((float*)(smp + SM_BIAS))[tid] = bias[tid];

    const float4* __restrict__ xb = (const float4*)(g_xT + (size_t)b * HW * CIN);

    float acc[4][8][4];
#pragma unroll
    for (int mi = 0; mi < 4; ++mi)
#pragma unroll
        for (int ni = 0; ni < 8; ++ni)
#pragma unroll
            for (int q = 0; q < 4; ++q) acc[mi][ni][q] = 0.0f;

    const uint32_t a_row_in_warp = (uint32_t)(lane & 15);
    const uint32_t a_koff        = (uint32_t)((lane >> 4) << 4);
    const uint32_t b_n_in_pair   = (uint32_t)(((lane >> 4) & 1) * 8 + (lane & 7));
    const uint32_t b_koff        = (uint32_t)(((lane >> 3) & 1) << 4);

    // ---- prologue: prefetch Whi(0), gather A(0) into buf0 ----
    stageW_async(sb + SM_WHI, g_Whi, tid);
    cp_commit();
    gather_half(gridp, xb, smp + SM_A0, p0, 0, 0, lane, warp);
    gather_half(gridp, xb, smp + SM_A0, p0, 0, 1, lane, warp);
    cp_wait0();
    __syncthreads();

    for (int t = 0; t < 9; ++t) {
        const int cur = t & 1;
        const uint32_t Acur = sb + (cur ? SM_A1 : SM_A0);
        char* const Anxt = smp + (cur ? SM_A0 : SM_A1);

        // prefetch Wlo(t) while pass-hi runs
        stageW_async(sb + SM_WLO, g_Wlo + (size_t)t * 65536, tid);
        cp_commit();

        // pass hi: acc += A(t) * Whi(t)
        mma_pass(Acur, sb + SM_WHI, acc, a_row_in_warp, a_koff, b_n_in_pair, b_koff,
                 warp_m, warp_n);

        // gather first half of A(t+1) (overlaps pass-hi tensor drain)
        if (t < 8) gather_half(gridp, xb, Anxt, p0, t + 1, 0, lane, warp);

        cp_wait0();          // Wlo(t) ready
        __syncthreads();     // all warps done reading Whi(t)

        // prefetch Whi(t+1) while pass-lo runs
        if (t < 8) {
            stageW_async(sb + SM_WHI, g_Whi + (size_t)(t + 1) * 65536, tid);
            cp_commit();
        }

        // pass lo: acc += A(t) * Wlo(t)
        mma_pass(Acur, sb + SM_WLO, acc, a_row_in_warp, a_koff, b_n_in_pair, b_koff,
                 warp_m, warp_n);

        // gather second half of A(t+1)
        if (t < 8) gather_half(gridp, xb, Anxt, p0, t + 1, 1, lane, warp);

        cp_wait0();          // Whi(t+1) ready
        __syncthreads();     // pass-lo + gather(t+1) complete
    }

    // ---- epilogue: acc -> Dsm[co][px] -> coalesced out ----
    float* Dsm = (float*)smp;   // 256 x 128 fp32 = 128KB (reuses A/W)
    {
        const int rbase = warp_m * 64 + (lane >> 2);
        const int cbase = warp_n * 64 + 2 * (lane & 3);
#pragma unroll
        for (int mi = 0; mi < 4; ++mi) {
#pragma unroll
            for (int ni = 0; ni < 8; ++ni) {
                const int rr = rbase + mi * 16;
                const int cc = cbase + ni * 8;
                Dsm[(cc    ) * 128 + rr    ] = acc[mi][ni][0];
                Dsm[(cc + 1) * 128 + rr    ] = acc[mi][ni][1];
                Dsm[(cc    ) * 128 + rr + 8] = acc[mi][ni][2];
                Dsm[(cc + 1) * 128 + rr + 8] = acc[mi][ni][3];
            }
        }
    }
    __syncthreads();

    {
        const float* bs = (const float*)(smp + SM_BIAS);
        float* ob = out + (size_t)b * COUT * HW + p0;
#pragma unroll 4
        for (int it = 0; it < 32; ++it) {
            const int co = it * 8 + warp;
            const float bv = bs[co];
            float4 v = ((const float4*)(Dsm + co * 128))[lane];
            v.x += bv; v.y += bv; v.z += bv; v.w += bv;
            ((float4*)(ob + (size_t)co * HW))[lane] = v;
        }
    }
}

// ---------------------------------------------------------------------------
extern "C" void kernel_launch(void* const* d_in, const int* in_sizes, int n_in,
                              void* d_out, int out_size) {
    const float* x      = (const float*)d_in[0];   // (4,128,128,256)
    const float* weight = (const float*)d_in[1];   // (256,128,3,3)
    const float* bias   = (const float*)d_in[2];   // (256,)
    const float* grid   = (const float*)d_in[3];   // (1,384,768,2)
    float* out = (float*)d_out;                    // (4,256,128,256)

    cudaFuncSetAttribute(sphere_hmma_kernel,
                         cudaFuncAttributeMaxDynamicSharedMemorySize, SM_TOTAL);

    {
        dim3 g(HW / 32, CIN / 32, B_);
        dim3 blk(32, 8);
        transpose_x_kernel<<<g, blk>>>(x);
    }
    weight_prep_f16_kernel<<<(9 * 256 * 128 + 255) / 256, 256>>>(weight);
    sphere_hmma_kernel<<<NTILES, 256, SM_TOTAL>>>(grid, bias, out);
}

// round 5
// speedup vs baseline: 3.7416x; 1.2212x over previous
#include <cuda_runtime.h>
#include <cuda_fp16.h>
#include <cstdint>
#include <math.h>

// ---------------- problem constants ----------------
#define B_   4
#define CIN  128
#define COUT 256
#define H_   128
#define W_   256
#define HW   (H_ * W_)              // 32768
#define TILE_M 128                  // pixels per CTA
#define NTILES (B_ * HW / TILE_M)   // 1024

// ---------------- device scratch ----------------
__device__ float g_xT[(size_t)B_ * HW * CIN];        // 64 MB (B, HW, Cin)
__device__ unsigned char g_Wf16[9 * 65536];          // per tap: 256 co x 256B (128 fp16), swizzled

// ---------------- smem layout (1024-aligned base) ----------------
#define SM_A0   0            // 128 rows x 256B = 32KB
#define SM_A1   32768        // 32KB
#define SM_W0   65536        // 64KB
#define SM_W1   131072       // 64KB
#define SM_BIAS 196608       // 1KB
#define SM_TOTAL (197632 + 1024)
// epilogue reuses [0, 128KB) as Dsm[co][px] fp32

__device__ __forceinline__ uint32_t bswz(uint32_t row, uint32_t col) {
    return col ^ ((row & 7u) << 4);
}

__device__ __forceinline__ uint32_t smem_u32(const void* p) {
    uint32_t a;
    asm("{ .reg .u64 t; cvta.to.shared.u64 t, %1; cvt.u32.u64 %0, t; }" : "=r"(a) : "l"(p));
    return a;
}

__device__ __forceinline__ void ldm_x4(uint32_t& r0, uint32_t& r1, uint32_t& r2, uint32_t& r3,
                                       uint32_t addr) {
    asm volatile("ldmatrix.sync.aligned.m8n8.x4.shared.b16 {%0,%1,%2,%3}, [%4];"
                 : "=r"(r0), "=r"(r1), "=r"(r2), "=r"(r3) : "r"(addr));
}

__device__ __forceinline__ void mma_16816(float& c0, float& c1, float& c2, float& c3,
                                          uint32_t a0, uint32_t a1, uint32_t a2, uint32_t a3,
                                          uint32_t b0, uint32_t b1) {
    asm volatile(
        "mma.sync.aligned.m16n8k16.row.col.f32.f16.f16.f32 "
        "{%0,%1,%2,%3}, {%4,%5,%6,%7}, {%8,%9}, {%0,%1,%2,%3};"
        : "+f"(c0), "+f"(c1), "+f"(c2), "+f"(c3)
        : "r"(a0), "r"(a1), "r"(a2), "r"(a3), "r"(b0), "r"(b1));
}

__device__ __forceinline__ void cp_async16(uint32_t dst, const void* src) {
    asm volatile("cp.async.cg.shared.global [%0], [%1], 16;" :: "r"(dst), "l"(src) : "memory");
}
__device__ __forceinline__ void cp_commit() {
    asm volatile("cp.async.commit_group;" ::: "memory");
}
__device__ __forceinline__ void cp_wait0() {
    asm volatile("cp.async.wait_group 0;" ::: "memory");
}

// stage a 64KB pre-swizzled W block (gmem linear -> smem linear), non-blocking
__device__ __forceinline__ void stageW_async(uint32_t smem_dst, const unsigned char* src, int tid) {
#pragma unroll
    for (int i = 0; i < 16; ++i) {
        cp_async16(smem_dst + i * 4096 + tid * 16, src + i * 4096 + tid * 16);
    }
}

// ---------------------------------------------------------------------------
// Kernel 1: transpose x (B, Cin, H, W) -> g_xT (B, HW, Cin)
// ---------------------------------------------------------------------------
__global__ void transpose_x_kernel(const float* __restrict__ x) {
    __shared__ float tile[32][33];
    const int b    = blockIdx.z;
    const int cin0 = blockIdx.y * 32;
    const int p0   = blockIdx.x * 32;
    const int tx = threadIdx.x, ty = threadIdx.y;   // 32 x 8
#pragma unroll
    for (int j = 0; j < 4; ++j)
        tile[ty + 8 * j][tx] = x[((size_t)b * CIN + (cin0 + ty + 8 * j)) * HW + (p0 + tx)];
    __syncthreads();
#pragma unroll
    for (int j = 0; j < 4; ++j)
        g_xT[((size_t)b * HW + (p0 + ty + 8 * j)) * CIN + (cin0 + tx)] = tile[tx][ty + 8 * j];
}

// ---------------------------------------------------------------------------
// Kernel 2: weight prep -> fp16 per tap, 256 co rows x 128 fp16, swizzled
// ---------------------------------------------------------------------------
__global__ void weight_prep_f16_kernel(const float* __restrict__ wsrc) {
    const int idx = blockIdx.x * 256 + threadIdx.x;   // < 9*256*128
    if (idx >= 9 * 256 * 128) return;
    const int cin = idx & 127;
    const int co  = (idx >> 7) & 255;
    const int t   = idx >> 15;
    const float v = wsrc[(co * CIN + cin) * 9 + t];
    const uint32_t off = (uint32_t)co * 256 + bswz(co, (uint32_t)cin * 2);
    *(__half*)(g_Wf16 + (size_t)t * 65536 + off) = __float2half(v);
}

// ---------------------------------------------------------------------------
// gather full tile (128 px) of tap `tap` into A buffer (fp16, swizzled)
// ---------------------------------------------------------------------------
__device__ __forceinline__ void gather_tile(const float* __restrict__ gridp,
                                            const float4* __restrict__ xb,
                                            char* abuf, int p0, int tap,
                                            int lane, int warp) {
    const int r = tap / 3;
    const int c = tap - r * 3;
#pragma unroll 1
    for (int i = 0; i < 16; ++i) {
        const int pp = i * 8 + warp;
        const int p = p0 + pp;
        const int h = p >> 8;
        const int w = p & 255;

        const int gi = (h * 3 + r) * (W_ * 3) + (w * 3 + c);
        const float gx = gridp[2 * gi + 0];
        const float gy = gridp[2 * gi + 1];

        const float ix = ((gx + 1.0f) * (float)W_ - 1.0f) * 0.5f;
        const float iy = ((gy + 1.0f) * (float)H_ - 1.0f) * 0.5f;
        const float x0f = floorf(ix), y0f = floorf(iy);
        const float fx = ix - x0f, fy = iy - y0f;
        const int xx0 = (int)x0f, yy0 = (int)y0f;
        const int xx1 = xx0 + 1, yy1 = yy0 + 1;

        float w00 = (1.0f - fx) * (1.0f - fy);
        float w10 = fx * (1.0f - fy);
        float w01 = (1.0f - fx) * fy;
        float w11 = fx * fy;
        if (xx0 < 0 || xx0 >= W_) { w00 = 0.0f; w01 = 0.0f; }
        if (xx1 < 0 || xx1 >= W_) { w10 = 0.0f; w11 = 0.0f; }
        if (yy0 < 0 || yy0 >= H_) { w00 = 0.0f; w10 = 0.0f; }
        if (yy1 < 0 || yy1 >= H_) { w01 = 0.0f; w11 = 0.0f; }

        const int xi0 = min(max(xx0, 0), W_ - 1);
        const int xi1 = min(max(xx1, 0), W_ - 1);
        const int yi0 = min(max(yy0, 0), H_ - 1);
        const int yi1 = min(max(yy1, 0), H_ - 1);

        const float4 v00 = xb[(size_t)(yi0 * W_ + xi0) * 32 + lane];
        const float4 v10 = xb[(size_t)(yi0 * W_ + xi1) * 32 + lane];
        const float4 v01 = xb[(size_t)(yi1 * W_ + xi0) * 32 + lane];
        const float4 v11 = xb[(size_t)(yi1 * W_ + xi1) * 32 + lane];

        float4 sv;
        sv.x = w00 * v00.x + w10 * v10.x + w01 * v01.x + w11 * v11.x;
        sv.y = w00 * v00.y + w10 * v10.y + w01 * v01.y + w11 * v11.y;
        sv.z = w00 * v00.z + w10 * v10.z + w01 * v01.z + w11 * v11.z;
        sv.w = w00 * v00.w + w10 * v10.w + w01 * v01.w + w11 * v11.w;

        const __half hx = __float2half(sv.x);
        const __half hy = __float2half(sv.y);
        const __half hz = __float2half(sv.z);
        const __half hw2 = __float2half(sv.w);

        const uint32_t h01 = (uint32_t)__half_as_ushort(hx) |
                             ((uint32_t)__half_as_ushort(hy) << 16);
        const uint32_t h23 = (uint32_t)__half_as_ushort(hz) |
                             ((uint32_t)__half_as_ushort(hw2) << 16);

        const uint32_t off = (uint32_t)pp * 256 + bswz((uint32_t)pp, (uint32_t)lane * 8);
        *(uint2*)(abuf + off) = make_uint2(h01, h23);
    }
}

// ---------------------------------------------------------------------------
// one MMA pass: A[128x128] x W[256x128]^T, K=128 (8 ksteps), warp tile 64x64
// ---------------------------------------------------------------------------
__device__ __forceinline__ void mma_pass(uint32_t Abase, uint32_t Wbase,
                                         float (*acc)[8][4],
                                         uint32_t a_row_in_warp, uint32_t a_koff,
                                         uint32_t b_n_in_pair, uint32_t b_koff,
                                         int warp_m, int warp_n) {
#pragma unroll
    for (int k0 = 0; k0 < 8; ++k0) {
        const uint32_t kb = (uint32_t)k0 * 32;

        uint32_t bfr[8][2];
#pragma unroll
        for (int np = 0; np < 4; ++np) {
            const uint32_t n = (uint32_t)(warp_n * 64 + np * 16) + b_n_in_pair;
            const uint32_t addr = Wbase + n * 256 + bswz(n, kb + b_koff);
            ldm_x4(bfr[np * 2][0], bfr[np * 2][1],
                   bfr[np * 2 + 1][0], bfr[np * 2 + 1][1], addr);
        }

#pragma unroll
        for (int mi = 0; mi < 4; ++mi) {
            const uint32_t row = (uint32_t)(warp_m * 64 + mi * 16) + a_row_in_warp;
            const uint32_t addr = Abase + row * 256 + bswz(row, kb + a_koff);
            uint32_t a0, a1, a2, a3;
            ldm_x4(a0, a1, a2, a3, addr);
#pragma unroll
            for (int ni = 0; ni < 8; ++ni) {
                mma_16816(acc[mi][ni][0], acc[mi][ni][1],
                          acc[mi][ni][2], acc[mi][ni][3],
                          a0, a1, a2, a3, bfr[ni][0], bfr[ni][1]);
            }
        }
    }
}

// ---------------------------------------------------------------------------
// Kernel 3: pipelined gather + single-pass fp16 ldmatrix/mma implicit GEMM.
// Per tap: ONE mma pass; W(t+1) prefetched via cp.async into alternate W
// buffer during the pass; A(t+1) gathered into alternate A buffer during the
// pass; one __syncthreads per tap.
// ---------------------------------------------------------------------------
__global__ __launch_bounds__(256, 1)
void sphere_hmma_kernel(const float* __restrict__ gridp,
                        const float* __restrict__ bias,
                        float* __restrict__ out) {
    extern __shared__ char dsm[];
    const uint32_t raw = smem_u32(dsm);
    const uint32_t sb  = (raw + 1023u) & ~1023u;
    char* const smp = dsm + (sb - raw);

    const int tid  = threadIdx.x;
    const int lane = tid & 31;
    const int warp = tid >> 5;
    const int warp_m = warp >> 2;       // 0..1
    const int warp_n = warp & 3;        // 0..3
    const int tile = blockIdx.x;
    const int b    = tile >> 8;
    const int p0   = (tile & 255) * TILE_M;

    ((float*)(smp + SM_BIAS))[tid] = bias[tid];

    const float4* __restrict__ xb = (const float4*)(g_xT + (size_t)b * HW * CIN);

    float acc[4][8][4];
#pragma unroll
    for (int mi = 0; mi < 4; ++mi)
#pragma unroll
        for (int ni = 0; ni < 8; ++ni)
#pragma unroll
            for (int q = 0; q < 4; ++q) acc[mi][ni][q] = 0.0f;

    const uint32_t a_row_in_warp = (uint32_t)(lane & 15);
    const uint32_t a_koff        = (uint32_t)((lane >> 4) << 4);
    const uint32_t b_n_in_pair   = (uint32_t)(((lane >> 4) & 1) * 8 + (lane & 7));
    const uint32_t b_koff        = (uint32_t)(((lane >> 3) & 1) << 4);

    // ---- prologue: prefetch W(0), gather A(0) ----
    stageW_async(sb + SM_W0, g_Wf16, tid);
    cp_commit();
    gather_tile(gridp, xb, smp + SM_A0, p0, 0, lane, warp);
    cp_wait0();
    __syncthreads();

    for (int t = 0; t < 9; ++t) {
        const int cur = t & 1;
        const uint32_t Acur = sb + (cur ? SM_A1 : SM_A0);
        const uint32_t Wcur = sb + (cur ? SM_W1 : SM_W0);
        char* const Anxt = smp + (cur ? SM_A0 : SM_A1);
        const uint32_t Wnxt = sb + (cur ? SM_W0 : SM_W1);

        // prefetch W(t+1) into the other buffer (runs under the MMA pass)
        if (t < 8) {
            stageW_async(Wnxt, g_Wf16 + (size_t)(t + 1) * 65536, tid);
            cp_commit();
        }

        // MMA pass: acc += A(t) * W(t)
        mma_pass(Acur, Wcur, acc, a_row_in_warp, a_koff, b_n_in_pair, b_koff,
                 warp_m, warp_n);

        // gather A(t+1) into the other buffer (overlaps tensor drain)
        if (t < 8) {
            gather_tile(gridp, xb, Anxt, p0, t + 1, lane, warp);
            cp_wait0();       // W(t+1) landed
        }
        __syncthreads();      // everyone done: reads of A(t)/W(t) + writes of t+1
    }

    // ---- epilogue: acc -> Dsm[co][px] -> coalesced out ----
    float* Dsm = (float*)smp;   // 256 x 128 fp32 = 128KB (reuses A/W)
    {
        const int rbase = warp_m * 64 + (lane >> 2);
        const int cbase = warp_n * 64 + 2 * (lane & 3);
#pragma unroll
        for (int mi = 0; mi < 4; ++mi) {
#pragma unroll
            for (int ni = 0; ni < 8; ++ni) {
                const int rr = rbase + mi * 16;
                const int cc = cbase + ni * 8;
                Dsm[(cc    ) * 128 + rr    ] = acc[mi][ni][0];
                Dsm[(cc + 1) * 128 + rr    ] = acc[mi][ni][1];
                Dsm[(cc    ) * 128 + rr + 8] = acc[mi][ni][2];
                Dsm[(cc + 1) * 128 + rr + 8] = acc[mi][ni][3];
            }
        }
    }
    __syncthreads();

    {
        const float* bs = (const float*)(smp + SM_BIAS);
        float* ob = out + (size_t)b * COUT * HW + p0;
#pragma unroll 4
        for (int it = 0; it < 32; ++it) {
            const int co = it * 8 + warp;
            const float bv = bs[co];
            float4 v = ((const float4*)(Dsm + co * 128))[lane];
            v.x += bv; v.y += bv; v.z += bv; v.w += bv;
            ((float4*)(ob + (size_t)co * HW))[lane] = v;
        }
    }
}

// ---------------------------------------------------------------------------
extern "C" void kernel_launch(void* const* d_in, const int* in_sizes, int n_in,
                              void* d_out, int out_size) {
    const float* x      = (const float*)d_in[0];   // (4,128,128,256)
    const float* weight = (const float*)d_in[1];   // (256,128,3,3)
    const float* bias   = (const float*)d_in[2];   // (256,)
    const float* grid   = (const float*)d_in[3];   // (1,384,768,2)
    float* out = (float*)d_out;                    // (4,256,128,256)

    cudaFuncSetAttribute(sphere_hmma_kernel,
                         cudaFuncAttributeMaxDynamicSharedMemorySize, SM_TOTAL);

    {
        dim3 g(HW / 32, CIN / 32, B_);
        dim3 blk(32, 8);
        transpose_x_kernel<<<g, blk>>>(x);
    }
    weight_prep_f16_kernel<<<(9 * 256 * 128 + 255) / 256, 256>>>(weight);
    sphere_hmma_kernel<<<NTILES, 256, SM_TOTAL>>>(grid, bias, out);
}

// round 6
// speedup vs baseline: 5.0966x; 1.3621x over previous
#include <cuda_runtime.h>
#include <cuda_fp16.h>
#include <cstdint>
#include <math.h>

// ---------------- problem constants ----------------
#define B_   4
#define CIN  128
#define COUT 256
#define H_   128
#define W_   256
#define HW   (H_ * W_)              // 32768
#define TILE_M 128                  // pixels per CTA
#define NTILES (B_ * HW / TILE_M)   // 1024

// ---------------- device scratch ----------------
__device__ __half g_xh[(size_t)B_ * HW * CIN];       // 32 MB (B, HW, Cin) fp16
__device__ unsigned char g_Wf16[9 * 65536];          // per tap: 256 co x 256B (128 fp16), swizzled
__device__ int4   g_tabI[9 * HW];                    // gather indices (in uint2 units of g_xh)
__device__ float4 g_tabW[9 * HW];                    // bilinear weights (edge-zeroed)

// ---------------- smem layout (1024-aligned base) ----------------
#define SM_A0   0            // 128 rows x 256B = 32KB
#define SM_A1   32768        // 32KB
#define SM_W0   65536        // 64KB
#define SM_W1   131072       // 64KB
#define SM_BIAS 196608       // 1KB
#define SM_TOTAL (197632 + 1024)
// epilogue reuses [0, 128KB) as Dsm[co][px] fp32

__device__ __forceinline__ uint32_t bswz(uint32_t row, uint32_t col) {
    return col ^ ((row & 7u) << 4);
}

__device__ __forceinline__ uint32_t smem_u32(const void* p) {
    uint32_t a;
    asm("{ .reg .u64 t; cvta.to.shared.u64 t, %1; cvt.u32.u64 %0, t; }" : "=r"(a) : "l"(p));
    return a;
}

__device__ __forceinline__ void ldm_x4(uint32_t& r0, uint32_t& r1, uint32_t& r2, uint32_t& r3,
                                       uint32_t addr) {
    asm volatile("ldmatrix.sync.aligned.m8n8.x4.shared.b16 {%0,%1,%2,%3}, [%4];"
                 : "=r"(r0), "=r"(r1), "=r"(r2), "=r"(r3) : "r"(addr));
}

__device__ __forceinline__ void mma_16816(float& c0, float& c1, float& c2, float& c3,
                                          uint32_t a0, uint32_t a1, uint32_t a2, uint32_t a3,
                                          uint32_t b0, uint32_t b1) {
    asm volatile(
        "mma.sync.aligned.m16n8k16.row.col.f32.f16.f16.f32 "
        "{%0,%1,%2,%3}, {%4,%5,%6,%7}, {%8,%9}, {%0,%1,%2,%3};"
        : "+f"(c0), "+f"(c1), "+f"(c2), "+f"(c3)
        : "r"(a0), "r"(a1), "r"(a2), "r"(a3), "r"(b0), "r"(b1));
}

__device__ __forceinline__ void cp_async16(uint32_t dst, const void* src) {
    asm volatile("cp.async.cg.shared.global [%0], [%1], 16;" :: "r"(dst), "l"(src) : "memory");
}
__device__ __forceinline__ void cp_commit() {
    asm volatile("cp.async.commit_group;" ::: "memory");
}
__device__ __forceinline__ void cp_wait0() {
    asm volatile("cp.async.wait_group 0;" ::: "memory");
}

__device__ __forceinline__ void stageW_async(uint32_t smem_dst, const unsigned char* src, int tid) {
#pragma unroll
    for (int i = 0; i < 16; ++i) {
        cp_async16(smem_dst + i * 4096 + tid * 16, src + i * 4096 + tid * 16);
    }
}

// ---------------------------------------------------------------------------
// Kernel 1: transpose+convert x (B, Cin, H, W) fp32 -> g_xh (B, HW, Cin) fp16
// ---------------------------------------------------------------------------
__global__ void transpose_x_kernel(const float* __restrict__ x) {
    __shared__ float tile[32][33];
    const int b    = blockIdx.z;
    const int cin0 = blockIdx.y * 32;
    const int p0   = blockIdx.x * 32;
    const int tx = threadIdx.x, ty = threadIdx.y;   // 32 x 8
#pragma unroll
    for (int j = 0; j < 4; ++j)
        tile[ty + 8 * j][tx] = x[((size_t)b * CIN + (cin0 + ty + 8 * j)) * HW + (p0 + tx)];
    __syncthreads();
#pragma unroll
    for (int j = 0; j < 4; ++j)
        g_xh[((size_t)b * HW + (p0 + ty + 8 * j)) * CIN + (cin0 + tx)] =
            __float2half(tile[tx][ty + 8 * j]);
}

// ---------------------------------------------------------------------------
// Kernel 2: weight prep -> fp16 per tap, 256 co rows x 128 fp16, swizzled
// ---------------------------------------------------------------------------
__global__ void weight_prep_f16_kernel(const float* __restrict__ wsrc) {
    const int idx = blockIdx.x * 256 + threadIdx.x;   // < 9*256*128
    if (idx >= 9 * 256 * 128) return;
    const int cin = idx & 127;
    const int co  = (idx >> 7) & 255;
    const int t   = idx >> 15;
    const float v = wsrc[(co * CIN + cin) * 9 + t];
    const uint32_t off = (uint32_t)co * 256 + bswz(co, (uint32_t)cin * 2);
    *(__half*)(g_Wf16 + (size_t)t * 65536 + off) = __float2half(v);
}

// ---------------------------------------------------------------------------
// Kernel 2b: grid prep. For each (tap, pixel): 4 clamped gather indices
// (in uint2=8B units over g_xh rows) + 4 edge-zeroed bilinear weights.
// ---------------------------------------------------------------------------
__global__ void grid_prep_kernel(const float* __restrict__ gridp) {
    const int idx = blockIdx.x * 256 + threadIdx.x;   // < 9*HW
    if (idx >= 9 * HW) return;
    const int p = idx & (HW - 1);
    const int t = idx >> 15;
    const int h = p >> 8;
    const int w = p & 255;
    const int r = t / 3;
    const int c = t - r * 3;

    const int gi = (h * 3 + r) * (W_ * 3) + (w * 3 + c);
    const float gx = gridp[2 * gi + 0];
    const float gy = gridp[2 * gi + 1];

    const float ix = ((gx + 1.0f) * (float)W_ - 1.0f) * 0.5f;
    const float iy = ((gy + 1.0f) * (float)H_ - 1.0f) * 0.5f;
    const float x0f = floorf(ix), y0f = floorf(iy);
    const float fx = ix - x0f, fy = iy - y0f;
    const int xx0 = (int)x0f, yy0 = (int)y0f;
    const int xx1 = xx0 + 1, yy1 = yy0 + 1;

    float w00 = (1.0f - fx) * (1.0f - fy);
    float w10 = fx * (1.0f - fy);
    float w01 = (1.0f - fx) * fy;
    float w11 = fx * fy;
    if (xx0 < 0 || xx0 >= W_) { w00 = 0.0f; w01 = 0.0f; }
    if (xx1 < 0 || xx1 >= W_) { w10 = 0.0f; w11 = 0.0f; }
    if (yy0 < 0 || yy0 >= H_) { w00 = 0.0f; w10 = 0.0f; }
    if (yy1 < 0 || yy1 >= H_) { w01 = 0.0f; w11 = 0.0f; }

    const int xi0 = min(max(xx0, 0), W_ - 1);
    const int xi1 = min(max(xx1, 0), W_ - 1);
    const int yi0 = min(max(yy0, 0), H_ - 1);
    const int yi1 = min(max(yy1, 0), H_ - 1);

    // uint2 units: each pixel row = 128 halves = 32 uint2
    int4 e;
    e.x = (yi0 * W_ + xi0) * 32;
    e.y = (yi0 * W_ + xi1) * 32;
    e.z = (yi1 * W_ + xi0) * 32;
    e.w = (yi1 * W_ + xi1) * 32;
    g_tabI[idx] = e;
    g_tabW[idx] = make_float4(w00, w10, w01, w11);
}

// ---------------------------------------------------------------------------
// gather full tile (128 px) of tap `tap` into A buffer (fp16, swizzled)
// table-driven: per px = 2 uniform 16B loads + 4 x 8B gather loads.
// ---------------------------------------------------------------------------
__device__ __forceinline__ void gather_tile(const uint2* __restrict__ xh2,
                                            char* abuf, int p0, int tap,
                                            int lane, int warp) {
    const int4*   __restrict__ tI = g_tabI + tap * HW + p0;
    const float4* __restrict__ tW = g_tabW + tap * HW + p0;
#pragma unroll 2
    for (int i = 0; i < 16; ++i) {
        const int pp = i * 8 + warp;
        const int4   e  = __ldg(tI + pp);
        const float4 wv = __ldg(tW + pp);

        const uint2 u00 = __ldg(xh2 + e.x + lane);
        const uint2 u10 = __ldg(xh2 + e.y + lane);
        const uint2 u01 = __ldg(xh2 + e.z + lane);
        const uint2 u11 = __ldg(xh2 + e.w + lane);

        const float2 a00 = __half22float2(*(const __half2*)&u00.x);
        const float2 b00 = __half22float2(*(const __half2*)&u00.y);
        const float2 a10 = __half22float2(*(const __half2*)&u10.x);
        const float2 b10 = __half22float2(*(const __half2*)&u10.y);
        const float2 a01 = __half22float2(*(const __half2*)&u01.x);
        const float2 b01 = __half22float2(*(const __half2*)&u01.y);
        const float2 a11 = __half22float2(*(const __half2*)&u11.x);
        const float2 b11 = __half22float2(*(const __half2*)&u11.y);

        float2 s0, s1;
        s0.x = wv.x * a00.x + wv.y * a10.x + wv.z * a01.x + wv.w * a11.x;
        s0.y = wv.x * a00.y + wv.y * a10.y + wv.z * a01.y + wv.w * a11.y;
        s1.x = wv.x * b00.x + wv.y * b10.x + wv.z * b01.x + wv.w * b11.x;
        s1.y = wv.x * b00.y + wv.y * b10.y + wv.z * b01.y + wv.w * b11.y;

        const __half2 h0 = __float22half2_rn(s0);
        const __half2 h1 = __float22half2_rn(s1);

        const uint32_t off = (uint32_t)pp * 256 + bswz((uint32_t)pp, (uint32_t)lane * 8);
        *(uint2*)(abuf + off) =
            make_uint2(*(const uint32_t*)&h0, *(const uint32_t*)&h1);
    }
}

// ---------------------------------------------------------------------------
// one MMA pass: A[128x128] x W[256x128]^T, K=128 (8 ksteps), warp tile 64x64
// ---------------------------------------------------------------------------
__device__ __forceinline__ void mma_pass(uint32_t Abase, uint32_t Wbase,
                                         float (*acc)[8][4],
                                         uint32_t a_row_in_warp, uint32_t a_koff,
                                         uint32_t b_n_in_pair, uint32_t b_koff,
                                         int warp_m, int warp_n) {
#pragma unroll
    for (int k0 = 0; k0 < 8; ++k0) {
        const uint32_t kb = (uint32_t)k0 * 32;

        uint32_t bfr[8][2];
#pragma unroll
        for (int np = 0; np < 4; ++np) {
            const uint32_t n = (uint32_t)(warp_n * 64 + np * 16) + b_n_in_pair;
            const uint32_t addr = Wbase + n * 256 + bswz(n, kb + b_koff);
            ldm_x4(bfr[np * 2][0], bfr[np * 2][1],
                   bfr[np * 2 + 1][0], bfr[np * 2 + 1][1], addr);
        }

#pragma unroll
        for (int mi = 0; mi < 4; ++mi) {
            const uint32_t row = (uint32_t)(warp_m * 64 + mi * 16) + a_row_in_warp;
            const uint32_t addr = Abase + row * 256 + bswz(row, kb + a_koff);
            uint32_t a0, a1, a2, a3;
            ldm_x4(a0, a1, a2, a3, addr);
#pragma unroll
            for (int ni = 0; ni < 8; ++ni) {
                mma_16816(acc[mi][ni][0], acc[mi][ni][1],
                          acc[mi][ni][2], acc[mi][ni][3],
                          a0, a1, a2, a3, bfr[ni][0], bfr[ni][1]);
            }
        }
    }
}

// ---------------------------------------------------------------------------
// Kernel 3: table-driven gather + single-pass fp16 mma, double-buffered.
// ---------------------------------------------------------------------------
__global__ __launch_bounds__(256, 1)
void sphere_hmma_kernel(const float* __restrict__ bias,
                        float* __restrict__ out) {
    extern __shared__ char dsm[];
    const uint32_t raw = smem_u32(dsm);
    const uint32_t sb  = (raw + 1023u) & ~1023u;
    char* const smp = dsm + (sb - raw);

    const int tid  = threadIdx.x;
    const int lane = tid & 31;
    const int warp = tid >> 5;
    const int warp_m = warp >> 2;       // 0..1
    const int warp_n = warp & 3;        // 0..3
    const int tile = blockIdx.x;
    const int b    = tile >> 8;
    const int p0   = (tile & 255) * TILE_M;

    ((float*)(smp + SM_BIAS))[tid] = bias[tid];

    const uint2* __restrict__ xh2 =
        (const uint2*)(g_xh + (size_t)b * HW * CIN);

    float acc[4][8][4];
#pragma unroll
    for (int mi = 0; mi < 4; ++mi)
#pragma unroll
        for (int ni = 0; ni < 8; ++ni)
#pragma unroll
            for (int q = 0; q < 4; ++q) acc[mi][ni][q] = 0.0f;

    const uint32_t a_row_in_warp = (uint32_t)(lane & 15);
    const uint32_t a_koff        = (uint32_t)((lane >> 4) << 4);
    const uint32_t b_n_in_pair   = (uint32_t)(((lane >> 4) & 1) * 8 + (lane & 7));
    const uint32_t b_koff        = (uint32_t)(((lane >> 3) & 1) << 4);

    // ---- prologue ----
    stageW_async(sb + SM_W0, g_Wf16, tid);
    cp_commit();
    gather_tile(xh2, smp + SM_A0, p0, 0, lane, warp);
    cp_wait0();
    __syncthreads();

    for (int t = 0; t < 9; ++t) {
        const int cur = t & 1;
        const uint32_t Acur = sb + (cur ? SM_A1 : SM_A0);
        const uint32_t Wcur = sb + (cur ? SM_W1 : SM_W0);
        char* const Anxt = smp + (cur ? SM_A0 : SM_A1);
        const uint32_t Wnxt = sb + (cur ? SM_W0 : SM_W1);

        if (t < 8) {
            stageW_async(Wnxt, g_Wf16 + (size_t)(t + 1) * 65536, tid);
            cp_commit();
        }

        mma_pass(Acur, Wcur, acc, a_row_in_warp, a_koff, b_n_in_pair, b_koff,
                 warp_m, warp_n);

        if (t < 8) {
            gather_tile(xh2, Anxt, p0, t + 1, lane, warp);
            cp_wait0();
        }
        __syncthreads();
    }

    // ---- epilogue: acc -> Dsm[co][px] -> coalesced out ----
    float* Dsm = (float*)smp;
    {
        const int rbase = warp_m * 64 + (lane >> 2);
        const int cbase = warp_n * 64 + 2 * (lane & 3);
#pragma unroll
        for (int mi = 0; mi < 4; ++mi) {
#pragma unroll
            for (int ni = 0; ni < 8; ++ni) {
                const int rr = rbase + mi * 16;
                const int cc = cbase + ni * 8;
                Dsm[(cc    ) * 128 + rr    ] = acc[mi][ni][0];
                Dsm[(cc + 1) * 128 + rr    ] = acc[mi][ni][1];
                Dsm[(cc    ) * 128 + rr + 8] = acc[mi][ni][2];
                Dsm[(cc + 1) * 128 + rr + 8] = acc[mi][ni][3];
            }
        }
    }
    __syncthreads();

    {
        const float* bs = (const float*)(smp + SM_BIAS);
        float* ob = out + (size_t)b * COUT * HW + p0;
#pragma unroll 4
        for (int it = 0; it < 32; ++it) {
            const int co = it * 8 + warp;
            const float bv = bs[co];
            float4 v = ((const float4*)(Dsm + co * 128))[lane];
            v.x += bv; v.y += bv; v.z += bv; v.w += bv;
            ((float4*)(ob + (size_t)co * HW))[lane] = v;
        }
    }
}

// ---------------------------------------------------------------------------
extern "C" void kernel_launch(void* const* d_in, const int* in_sizes, int n_in,
                              void* d_out, int out_size) {
    const float* x      = (const float*)d_in[0];   // (4,128,128,256)
    const float* weight = (const float*)d_in[1];   // (256,128,3,3)
    const float* bias   = (const float*)d_in[2];   // (256,)
    const float* grid   = (const float*)d_in[3];   // (1,384,768,2)
    float* out = (float*)d_out;                    // (4,256,128,256)

    cudaFuncSetAttribute(sphere_hmma_kernel,
                         cudaFuncAttributeMaxDynamicSharedMemorySize, SM_TOTAL);

    {
        dim3 g(HW / 32, CIN / 32, B_);
        dim3 blk(32, 8);
        transpose_x_kernel<<<g, blk>>>(x);
    }
    weight_prep_f16_kernel<<<(9 * 256 * 128 + 255) / 256, 256>>>(weight);
    grid_prep_kernel<<<(9 * HW + 255) / 256, 256>>>(grid);
    sphere_hmma_kernel<<<NTILES, 256, SM_TOTAL>>>(bias, out);
}

// round 7
// speedup vs baseline: 6.9072x; 1.3553x over previous
#include <cuda_runtime.h>
#include <cuda_fp16.h>
#include <cstdint>
#include <math.h>

// ---------------- problem constants ----------------
#define B_   4
#define CIN  128
#define COUT 256
#define H_   128
#define W_   256
#define HW   (H_ * W_)              // 32768
#define TILE_M 128                  // pixels per CTA
#define NTILES (B_ * HW / TILE_M)   // 1024
#define NTHREADS 512

// ---------------- device scratch ----------------
__device__ __half g_xh[(size_t)B_ * HW * CIN];       // 32 MB (B, HW, Cin) fp16
__device__ unsigned char g_Wf16[9 * 65536];          // per tap: 256 co x 256B (128 fp16), swizzled
__device__ int4   g_tabI[9 * HW];                    // gather indices (uint2 units into g_xh)
__device__ float4 g_tabW[9 * HW];                    // bilinear weights (edge-zeroed)

// ---------------- smem layout (1024-aligned base) ----------------
#define SM_A0   0            // 128 rows x 256B = 32KB
#define SM_A1   32768        // 32KB
#define SM_W0   65536        // 64KB
#define SM_W1   131072       // 64KB
#define SM_BIAS 196608       // 1KB
#define SM_TOTAL (197632 + 1024)
// epilogue reuses [0, 128KB) as Dsm[co][px] fp32

__device__ __forceinline__ uint32_t bswz(uint32_t row, uint32_t col) {
    return col ^ ((row & 7u) << 4);
}

__device__ __forceinline__ uint32_t smem_u32(const void* p) {
    uint32_t a;
    asm("{ .reg .u64 t; cvta.to.shared.u64 t, %1; cvt.u32.u64 %0, t; }" : "=r"(a) : "l"(p));
    return a;
}

__device__ __forceinline__ void ldm_x4(uint32_t& r0, uint32_t& r1, uint32_t& r2, uint32_t& r3,
                                       uint32_t addr) {
    asm volatile("ldmatrix.sync.aligned.m8n8.x4.shared.b16 {%0,%1,%2,%3}, [%4];"
                 : "=r"(r0), "=r"(r1), "=r"(r2), "=r"(r3) : "r"(addr));
}

__device__ __forceinline__ void mma_16816(float& c0, float& c1, float& c2, float& c3,
                                          uint32_t a0, uint32_t a1, uint32_t a2, uint32_t a3,
                                          uint32_t b0, uint32_t b1) {
    asm volatile(
        "mma.sync.aligned.m16n8k16.row.col.f32.f16.f16.f32 "
        "{%0,%1,%2,%3}, {%4,%5,%6,%7}, {%8,%9}, {%0,%1,%2,%3};"
        : "+f"(c0), "+f"(c1), "+f"(c2), "+f"(c3)
        : "r"(a0), "r"(a1), "r"(a2), "r"(a3), "r"(b0), "r"(b1));
}

__device__ __forceinline__ void cp_async16(uint32_t dst, const void* src) {
    asm volatile("cp.async.cg.shared.global [%0], [%1], 16;" :: "r"(dst), "l"(src) : "memory");
}
__device__ __forceinline__ void cp_commit() {
    asm volatile("cp.async.commit_group;" ::: "memory");
}
__device__ __forceinline__ void cp_wait0() {
    asm volatile("cp.async.wait_group 0;" ::: "memory");
}

// stage a 64KB pre-swizzled W block with 512 threads, non-blocking
__device__ __forceinline__ void stageW_async(uint32_t smem_dst, const unsigned char* src, int tid) {
#pragma unroll
    for (int i = 0; i < 8; ++i) {
        cp_async16(smem_dst + i * 8192 + tid * 16, src + i * 8192 + tid * 16);
    }
}

// ---------------------------------------------------------------------------
// Kernel 1: transpose+convert x (B, Cin, H, W) fp32 -> g_xh (B, HW, Cin) fp16
// ---------------------------------------------------------------------------
__global__ void transpose_x_kernel(const float* __restrict__ x) {
    __shared__ float tile[32][33];
    const int b    = blockIdx.z;
    const int cin0 = blockIdx.y * 32;
    const int p0   = blockIdx.x * 32;
    const int tx = threadIdx.x, ty = threadIdx.y;   // 32 x 8
#pragma unroll
    for (int j = 0; j < 4; ++j)
        tile[ty + 8 * j][tx] = x[((size_t)b * CIN + (cin0 + ty + 8 * j)) * HW + (p0 + tx)];
    __syncthreads();
#pragma unroll
    for (int j = 0; j < 4; ++j)
        g_xh[((size_t)b * HW + (p0 + ty + 8 * j)) * CIN + (cin0 + tx)] =
            __float2half(tile[tx][ty + 8 * j]);
}

// ---------------------------------------------------------------------------
// Kernel 2: weight prep -> fp16 per tap, 256 co rows x 128 fp16, swizzled
// ---------------------------------------------------------------------------
__global__ void weight_prep_f16_kernel(const float* __restrict__ wsrc) {
    const int idx = blockIdx.x * 256 + threadIdx.x;   // < 9*256*128
    if (idx >= 9 * 256 * 128) return;
    const int cin = idx & 127;
    const int co  = (idx >> 7) & 255;
    const int t   = idx >> 15;
    const float v = wsrc[(co * CIN + cin) * 9 + t];
    const uint32_t off = (uint32_t)co * 256 + bswz(co, (uint32_t)cin * 2);
    *(__half*)(g_Wf16 + (size_t)t * 65536 + off) = __float2half(v);
}

// ---------------------------------------------------------------------------
// Kernel 2b: grid prep -> clamped gather indices + edge-zeroed weights
// ---------------------------------------------------------------------------
__global__ void grid_prep_kernel(const float* __restrict__ gridp) {
    const int idx = blockIdx.x * 256 + threadIdx.x;   // < 9*HW
    if (idx >= 9 * HW) return;
    const int p = idx & (HW - 1);
    const int t = idx >> 15;
    const int h = p >> 8;
    const int w = p & 255;
    const int r = t / 3;
    const int c = t - r * 3;

    const int gi = (h * 3 + r) * (W_ * 3) + (w * 3 + c);
    const float gx = gridp[2 * gi + 0];
    const float gy = gridp[2 * gi + 1];

    const float ix = ((gx + 1.0f) * (float)W_ - 1.0f) * 0.5f;
    const float iy = ((gy + 1.0f) * (float)H_ - 1.0f) * 0.5f;
    const float x0f = floorf(ix), y0f = floorf(iy);
    const float fx = ix - x0f, fy = iy - y0f;
    const int xx0 = (int)x0f, yy0 = (int)y0f;
    const int xx1 = xx0 + 1, yy1 = yy0 + 1;

    float w00 = (1.0f - fx) * (1.0f - fy);
    float w10 = fx * (1.0f - fy);
    float w01 = (1.0f - fx) * fy;
    float w11 = fx * fy;
    if (xx0 < 0 || xx0 >= W_) { w00 = 0.0f; w01 = 0.0f; }
    if (xx1 < 0 || xx1 >= W_) { w10 = 0.0f; w11 = 0.0f; }
    if (yy0 < 0 || yy0 >= H_) { w00 = 0.0f; w10 = 0.0f; }
    if (yy1 < 0 || yy1 >= H_) { w01 = 0.0f; w11 = 0.0f; }

    const int xi0 = min(max(xx0, 0), W_ - 1);
    const int xi1 = min(max(xx1, 0), W_ - 1);
    const int yi0 = min(max(yy0, 0), H_ - 1);
    const int yi1 = min(max(yy1, 0), H_ - 1);

    int4 e;
    e.x = (yi0 * W_ + xi0) * 32;
    e.y = (yi0 * W_ + xi1) * 32;
    e.z = (yi1 * W_ + xi0) * 32;
    e.w = (yi1 * W_ + xi1) * 32;
    g_tabI[idx] = e;
    g_tabW[idx] = make_float4(w00, w10, w01, w11);
}

// ---------------------------------------------------------------------------
// gather full tile (128 px) of tap `tap` into A buffer; 16 warps, 8 px each
// ---------------------------------------------------------------------------
__device__ __forceinline__ void gather_tile(const uint2* __restrict__ xh2,
                                            char* abuf, int p0, int tap,
                                            int lane, int warp) {
    const int4*   __restrict__ tI = g_tabI + tap * HW + p0;
    const float4* __restrict__ tW = g_tabW + tap * HW + p0;
#pragma unroll 2
    for (int i = 0; i < 8; ++i) {
        const int pp = i * 16 + warp;
        const int4   e  = __ldg(tI + pp);
        const float4 wv = __ldg(tW + pp);

        const uint2 u00 = __ldg(xh2 + e.x + lane);
        const uint2 u10 = __ldg(xh2 + e.y + lane);
        const uint2 u01 = __ldg(xh2 + e.z + lane);
        const uint2 u11 = __ldg(xh2 + e.w + lane);

        const float2 a00 = __half22float2(*(const __half2*)&u00.x);
        const float2 b00 = __half22float2(*(const __half2*)&u00.y);
        const float2 a10 = __half22float2(*(const __half2*)&u10.x);
        const float2 b10 = __half22float2(*(const __half2*)&u10.y);
        const float2 a01 = __half22float2(*(const __half2*)&u01.x);
        const float2 b01 = __half22float2(*(const __half2*)&u01.y);
        const float2 a11 = __half22float2(*(const __half2*)&u11.x);
        const float2 b11 = __half22float2(*(const __half2*)&u11.y);

        float2 s0, s1;
        s0.x = wv.x * a00.x + wv.y * a10.x + wv.z * a01.x + wv.w * a11.x;
        s0.y = wv.x * a00.y + wv.y * a10.y + wv.z * a01.y + wv.w * a11.y;
        s1.x = wv.x * b00.x + wv.y * b10.x + wv.z * b01.x + wv.w * b11.x;
        s1.y = wv.x * b00.y + wv.y * b10.y + wv.z * b01.y + wv.w * b11.y;

        const __half2 h0 = __float22half2_rn(s0);
        const __half2 h1 = __float22half2_rn(s1);

        const uint32_t off = (uint32_t)pp * 256 + bswz((uint32_t)pp, (uint32_t)lane * 8);
        *(uint2*)(abuf + off) =
            make_uint2(*(const uint32_t*)&h0, *(const uint32_t*)&h1);
    }
}

// ---------------------------------------------------------------------------
// one MMA pass: warp tile 32(M) x 64(N), 4x4 warp grid, K=128 (8 ksteps)
// ---------------------------------------------------------------------------
__device__ __forceinline__ void mma_pass(uint32_t Abase, uint32_t Wbase,
                                         float (*acc)[8][4],
                                         uint32_t a_row_in_warp, uint32_t a_koff,
                                         uint32_t b_n_in_pair, uint32_t b_koff,
                                         int warp_m, int warp_n) {
#pragma unroll
    for (int k0 = 0; k0 < 8; ++k0) {
        const uint32_t kb = (uint32_t)k0 * 32;

        uint32_t bfr[8][2];
#pragma unroll
        for (int np = 0; np < 4; ++np) {
            const uint32_t n = (uint32_t)(warp_n * 64 + np * 16) + b_n_in_pair;
            const uint32_t addr = Wbase + n * 256 + bswz(n, kb + b_koff);
            ldm_x4(bfr[np * 2][0], bfr[np * 2][1],
                   bfr[np * 2 + 1][0], bfr[np * 2 + 1][1], addr);
        }

#pragma unroll
        for (int mi = 0; mi < 2; ++mi) {
            const uint32_t row = (uint32_t)(warp_m * 32 + mi * 16) + a_row_in_warp;
            const uint32_t addr = Abase + row * 256 + bswz(row, kb + a_koff);
            uint32_t a0, a1, a2, a3;
            ldm_x4(a0, a1, a2, a3, addr);
#pragma unroll
            for (int ni = 0; ni < 8; ++ni) {
                mma_16816(acc[mi][ni][0], acc[mi][ni][1],
                          acc[mi][ni][2], acc[mi][ni][3],
                          a0, a1, a2, a3, bfr[ni][0], bfr[ni][1]);
            }
        }
    }
}

// ---------------------------------------------------------------------------
// Kernel 3: table-driven gather + single-pass fp16 mma, 512 threads/16 warps
// ---------------------------------------------------------------------------
__global__ __launch_bounds__(NTHREADS, 1)
void sphere_hmma_kernel(const float* __restrict__ bias,
                        float* __restrict__ out) {
    extern __shared__ char dsm[];
    const uint32_t raw = smem_u32(dsm);
    const uint32_t sb  = (raw + 1023u) & ~1023u;
    char* const smp = dsm + (sb - raw);

    const int tid  = threadIdx.x;
    const int lane = tid & 31;
    const int warp = tid >> 5;          // 0..15
    const int warp_m = warp >> 2;       // 0..3
    const int warp_n = warp & 3;        // 0..3
    const int tile = blockIdx.x;
    const int b    = tile >> 8;
    const int p0   = (tile & 255) * TILE_M;

    if (tid < 256) ((float*)(smp + SM_BIAS))[tid] = bias[tid];

    const uint2* __restrict__ xh2 =
        (const uint2*)(g_xh + (size_t)b * HW * CIN);

    float acc[2][8][4];
#pragma unroll
    for (int mi = 0; mi < 2; ++mi)
#pragma unroll
        for (int ni = 0; ni < 8; ++ni)
#pragma unroll
            for (int q = 0; q < 4; ++q) acc[mi][ni][q] = 0.0f;

    const uint32_t a_row_in_warp = (uint32_t)(lane & 15);
    const uint32_t a_koff        = (uint32_t)((lane >> 4) << 4);
    const uint32_t b_n_in_pair   = (uint32_t)(((lane >> 4) & 1) * 8 + (lane & 7));
    const uint32_t b_koff        = (uint32_t)(((lane >> 3) & 1) << 4);

    // ---- prologue ----
    stageW_async(sb + SM_W0, g_Wf16, tid);
    cp_commit();
    gather_tile(xh2, smp + SM_A0, p0, 0, lane, warp);
    cp_wait0();
    __syncthreads();

    for (int t = 0; t < 9; ++t) {
        const int cur = t & 1;
        const uint32_t Acur = sb + (cur ? SM_A1 : SM_A0);
        const uint32_t Wcur = sb + (cur ? SM_W1 : SM_W0);
        char* const Anxt = smp + (cur ? SM_A0 : SM_A1);
        const uint32_t Wnxt = sb + (cur ? SM_W0 : SM_W1);

        if (t < 8) {
            stageW_async(Wnxt, g_Wf16 + (size_t)(t + 1) * 65536, tid);
            cp_commit();
        }

        mma_pass(Acur, Wcur, acc, a_row_in_warp, a_koff, b_n_in_pair, b_koff,
                 warp_m, warp_n);

        if (t < 8) {
            gather_tile(xh2, Anxt, p0, t + 1, lane, warp);
            cp_wait0();
        }
        __syncthreads();
    }

    // ---- epilogue: acc -> Dsm[co][px] -> coalesced out ----
    float* Dsm = (float*)smp;
    {
        const int rbase = warp_m * 32 + (lane >> 2);
        const int cbase = warp_n * 64 + 2 * (lane & 3);
#pragma unroll
        for (int mi = 0; mi < 2; ++mi) {
#pragma unroll
            for (int ni = 0; ni < 8; ++ni) {
                const int rr = rbase + mi * 16;
                const int cc = cbase + ni * 8;
                Dsm[(cc    ) * 128 + rr    ] = acc[mi][ni][0];
                Dsm[(cc + 1) * 128 + rr    ] = acc[mi][ni][1];
                Dsm[(cc    ) * 128 + rr + 8] = acc[mi][ni][2];
                Dsm[(cc + 1) * 128 + rr + 8] = acc[mi][ni][3];
            }
        }
    }
    __syncthreads();

    {
        const float* bs = (const float*)(smp + SM_BIAS);
        float* ob = out + (size_t)b * COUT * HW + p0;
#pragma unroll 4
        for (int it = 0; it < 16; ++it) {
            const int co = it * 16 + warp;
            const float bv = bs[co];
            float4 v = ((const float4*)(Dsm + co * 128))[lane];
            v.x += bv; v.y += bv; v.z += bv; v.w += bv;
            ((float4*)(ob + (size_t)co * HW))[lane] = v;
        }
    }
}

// ---------------------------------------------------------------------------
extern "C" void kernel_launch(void* const* d_in, const int* in_sizes, int n_in,
                              void* d_out, int out_size) {
    const float* x      = (const float*)d_in[0];   // (4,128,128,256)
    const float* weight = (const float*)d_in[1];   // (256,128,3,3)
    const float* bias   = (const float*)d_in[2];   // (256,)
    const float* grid   = (const float*)d_in[3];   // (1,384,768,2)
    float* out = (float*)d_out;                    // (4,256,128,256)

    cudaFuncSetAttribute(sphere_hmma_kernel,
                         cudaFuncAttributeMaxDynamicSharedMemorySize, SM_TOTAL);

    {
        dim3 g(HW / 32, CIN / 32, B_);
        dim3 blk(32, 8);
        transpose_x_kernel<<<g, blk>>>(x);
    }
    weight_prep_f16_kernel<<<(9 * 256 * 128 + 255) / 256, 256>>>(weight);
    grid_prep_kernel<<<(9 * HW + 255) / 256, 256>>>(grid);
    sphere_hmma_kernel<<<NTILES, NTHREADS, SM_TOTAL>>>(bias, out);
}

// round 8
// speedup vs baseline: 7.9677x; 1.1535x over previous
#include <cuda_runtime.h>
#include <cuda_fp16.h>
#include <cstdint>
#include <math.h>

// ---------------- problem constants ----------------
#define B_   4
#define CIN  128
#define COUT 256
#define H_   128
#define W_   256
#define HW   (H_ * W_)              // 32768
#define TILE_M 128                  // pixels per CTA
#define NTILES (B_ * HW / TILE_M)   // 1024
#define NTHREADS 512

// ---------------- device scratch ----------------
__device__ __half g_xh[(size_t)B_ * HW * CIN];       // 32 MB (B, HW, Cin) fp16
__device__ unsigned char g_Wf16[9 * 65536];          // per tap: 256 co x 256B (128 fp16), swizzled
__device__ int4   g_tabI[9 * HW];                    // gather indices (uint2 units into g_xh)
__device__ float4 g_tabW[9 * HW];                    // bilinear weights (edge-zeroed)

// ---------------- smem layout (1024-aligned base) ----------------
#define SM_A0   0            // 128 rows x 256B = 32KB
#define SM_A1   32768        // 32KB
#define SM_W0   65536        // 64KB
#define SM_W1   131072       // 64KB
#define SM_BIAS 196608       // 1KB
#define SM_TOTAL (197632 + 1024)
// epilogue reuses [0, 128KB) as Dsm[co][px] fp32

__device__ __forceinline__ uint32_t bswz(uint32_t row, uint32_t col) {
    return col ^ ((row & 7u) << 4);
}

__device__ __forceinline__ uint32_t smem_u32(const void* p) {
    uint32_t a;
    asm("{ .reg .u64 t; cvta.to.shared.u64 t, %1; cvt.u32.u64 %0, t; }" : "=r"(a) : "l"(p));
    return a;
}

__device__ __forceinline__ void ldm_x4(uint32_t& r0, uint32_t& r1, uint32_t& r2, uint32_t& r3,
                                       uint32_t addr) {
    asm volatile("ldmatrix.sync.aligned.m8n8.x4.shared.b16 {%0,%1,%2,%3}, [%4];"
                 : "=r"(r0), "=r"(r1), "=r"(r2), "=r"(r3) : "r"(addr));
}

__device__ __forceinline__ void mma_16816(float& c0, float& c1, float& c2, float& c3,
                                          uint32_t a0, uint32_t a1, uint32_t a2, uint32_t a3,
                                          uint32_t b0, uint32_t b1) {
    asm volatile(
        "mma.sync.aligned.m16n8k16.row.col.f32.f16.f16.f32 "
        "{%0,%1,%2,%3}, {%4,%5,%6,%7}, {%8,%9}, {%0,%1,%2,%3};"
        : "+f"(c0), "+f"(c1), "+f"(c2), "+f"(c3)
        : "r"(a0), "r"(a1), "r"(a2), "r"(a3), "r"(b0), "r"(b1));
}

__device__ __forceinline__ void cp_async16(uint32_t dst, const void* src) {
    asm volatile("cp.async.cg.shared.global [%0], [%1], 16;" :: "r"(dst), "l"(src) : "memory");
}
__device__ __forceinline__ void cp_commit() {
    asm volatile("cp.async.commit_group;" ::: "memory");
}
__device__ __forceinline__ void cp_wait0() {
    asm volatile("cp.async.wait_group 0;" ::: "memory");
}

// stage a 64KB pre-swizzled W block with 512 threads, non-blocking
__device__ __forceinline__ void stageW_async(uint32_t smem_dst, const unsigned char* src, int tid) {
#pragma unroll
    for (int i = 0; i < 8; ++i) {
        cp_async16(smem_dst + i * 8192 + tid * 16, src + i * 8192 + tid * 16);
    }
}

// ---------------------------------------------------------------------------
// Kernel 1: transpose+convert x (B, Cin, H, W) fp32 -> g_xh (B, HW, Cin) fp16
// ---------------------------------------------------------------------------
__global__ void transpose_x_kernel(const float* __restrict__ x) {
    __shared__ float tile[32][33];
    const int b    = blockIdx.z;
    const int cin0 = blockIdx.y * 32;
    const int p0   = blockIdx.x * 32;
    const int tx = threadIdx.x, ty = threadIdx.y;   // 32 x 8
#pragma unroll
    for (int j = 0; j < 4; ++j)
        tile[ty + 8 * j][tx] = x[((size_t)b * CIN + (cin0 + ty + 8 * j)) * HW + (p0 + tx)];
    __syncthreads();
#pragma unroll
    for (int j = 0; j < 4; ++j)
        g_xh[((size_t)b * HW + (p0 + ty + 8 * j)) * CIN + (cin0 + tx)] =
            __float2half(tile[tx][ty + 8 * j]);
}

// ---------------------------------------------------------------------------
// Kernel 2: weight prep -> fp16 per tap, 256 co rows x 128 fp16, swizzled
// ---------------------------------------------------------------------------
__global__ void weight_prep_f16_kernel(const float* __restrict__ wsrc) {
    const int idx = blockIdx.x * 256 + threadIdx.x;   // < 9*256*128
    if (idx >= 9 * 256 * 128) return;
    const int cin = idx & 127;
    const int co  = (idx >> 7) & 255;
    const int t   = idx >> 15;
    const float v = wsrc[(co * CIN + cin) * 9 + t];
    const uint32_t off = (uint32_t)co * 256 + bswz(co, (uint32_t)cin * 2);
    *(__half*)(g_Wf16 + (size_t)t * 65536 + off) = __float2half(v);
}

// ---------------------------------------------------------------------------
// Kernel 2b: grid prep -> clamped gather indices + edge-zeroed weights
// ---------------------------------------------------------------------------
__global__ void grid_prep_kernel(const float* __restrict__ gridp) {
    const int idx = blockIdx.x * 256 + threadIdx.x;   // < 9*HW
    if (idx >= 9 * HW) return;
    const int p = idx & (HW - 1);
    const int t = idx >> 15;
    const int h = p >> 8;
    const int w = p & 255;
    const int r = t / 3;
    const int c = t - r * 3;

    const int gi = (h * 3 + r) * (W_ * 3) + (w * 3 + c);
    const float gx = gridp[2 * gi + 0];
    const float gy = gridp[2 * gi + 1];

    const float ix = ((gx + 1.0f) * (float)W_ - 1.0f) * 0.5f;
    const float iy = ((gy + 1.0f) * (float)H_ - 1.0f) * 0.5f;
    const float x0f = floorf(ix), y0f = floorf(iy);
    const float fx = ix - x0f, fy = iy - y0f;
    const int xx0 = (int)x0f, yy0 = (int)y0f;
    const int xx1 = xx0 + 1, yy1 = yy0 + 1;

    float w00 = (1.0f - fx) * (1.0f - fy);
    float w10 = fx * (1.0f - fy);
    float w01 = (1.0f - fx) * fy;
    float w11 = fx * fy;
    if (xx0 < 0 || xx0 >= W_) { w00 = 0.0f; w01 = 0.0f; }
    if (xx1 < 0 || xx1 >= W_) { w10 = 0.0f; w11 = 0.0f; }
    if (yy0 < 0 || yy0 >= H_) { w00 = 0.0f; w10 = 0.0f; }
    if (yy1 < 0 || yy1 >= H_) { w01 = 0.0f; w11 = 0.0f; }

    const int xi0 = min(max(xx0, 0), W_ - 1);
    const int xi1 = min(max(xx1, 0), W_ - 1);
    const int yi0 = min(max(yy0, 0), H_ - 1);
    const int yi1 = min(max(yy1, 0), H_ - 1);

    int4 e;
    e.x = (yi0 * W_ + xi0) * 32;
    e.y = (yi0 * W_ + xi1) * 32;
    e.z = (yi1 * W_ + xi0) * 32;
    e.w = (yi1 * W_ + xi1) * 32;
    g_tabI[idx] = e;
    g_tabW[idx] = make_float4(w00, w10, w01, w11);
}

// ---------------------------------------------------------------------------
// fused tap: 8 k-steps of warp-tile (32x64) MMA, with the NEXT tap's gather
// interleaved 1 pixel per k-step (LDGs issued before the MMAs, blended after).
// ---------------------------------------------------------------------------
template <bool GATHER>
__device__ __forceinline__ void mma_tap_fused(
    uint32_t Abase, uint32_t Wbase, float (*acc)[8][4],
    const int4* __restrict__ tI, const float4* __restrict__ tW,
    const uint2* __restrict__ xh2, char* __restrict__ Anxt,
    uint32_t a_row_in_warp, uint32_t a_koff,
    uint32_t b_n_in_pair, uint32_t b_koff,
    int warp_m, int warp_n, int lane, int warp) {

    int4 e;
    float4 wv;
    if (GATHER) {           // table entry for pixel of k-step 0
        e  = __ldg(tI + warp);
        wv = __ldg(tW + warp);
    }

#pragma unroll
    for (int k0 = 0; k0 < 8; ++k0) {
        // ---- issue gather LDGs for pixel (k0*16 + warp) ----
        uint2 u00, u10, u01, u11;
        if (GATHER) {
            u00 = __ldg(xh2 + e.x + lane);
            u10 = __ldg(xh2 + e.y + lane);
            u01 = __ldg(xh2 + e.z + lane);
            u11 = __ldg(xh2 + e.w + lane);
        }

        const uint32_t kb = (uint32_t)k0 * 32;

        // ---- B fragments ----
        uint32_t bfr[8][2];
#pragma unroll
        for (int np = 0; np < 4; ++np) {
            const uint32_t n = (uint32_t)(warp_n * 64 + np * 16) + b_n_in_pair;
            const uint32_t addr = Wbase + n * 256 + bswz(n, kb + b_koff);
            ldm_x4(bfr[np * 2][0], bfr[np * 2][1],
                   bfr[np * 2 + 1][0], bfr[np * 2 + 1][1], addr);
        }

        // ---- A fragments ----
        uint32_t a0[2], a1[2], a2[2], a3[2];
#pragma unroll
        for (int mi = 0; mi < 2; ++mi) {
            const uint32_t row = (uint32_t)(warp_m * 32 + mi * 16) + a_row_in_warp;
            const uint32_t addr = Abase + row * 256 + bswz(row, kb + a_koff);
            ldm_x4(a0[mi], a1[mi], a2[mi], a3[mi], addr);
        }

        // ---- prefetch next table entry (consumed next k-step) ----
        int4 en;
        float4 wvn;
        if (GATHER && k0 < 7) {
            en  = __ldg(tI + (k0 + 1) * 16 + warp);
            wvn = __ldg(tW + (k0 + 1) * 16 + warp);
        }

        // ---- 16 MMAs ----
#pragma unroll
        for (int mi = 0; mi < 2; ++mi) {
#pragma unroll
            for (int ni = 0; ni < 8; ++ni) {
                mma_16816(acc[mi][ni][0], acc[mi][ni][1],
                          acc[mi][ni][2], acc[mi][ni][3],
                          a0[mi], a1[mi], a2[mi], a3[mi],
                          bfr[ni][0], bfr[ni][1]);
            }
        }

        // ---- blend + store gathered pixel ----
        if (GATHER) {
            const float2 a00 = __half22float2(*(const __half2*)&u00.x);
            const float2 b00 = __half22float2(*(const __half2*)&u00.y);
            const float2 a10 = __half22float2(*(const __half2*)&u10.x);
            const float2 b10 = __half22float2(*(const __half2*)&u10.y);
            const float2 a01 = __half22float2(*(const __half2*)&u01.x);
            const float2 b01 = __half22float2(*(const __half2*)&u01.y);
            const float2 a11 = __half22float2(*(const __half2*)&u11.x);
            const float2 b11 = __half22float2(*(const __half2*)&u11.y);

            float2 s0, s1;
            s0.x = wv.x * a00.x + wv.y * a10.x + wv.z * a01.x + wv.w * a11.x;
            s0.y = wv.x * a00.y + wv.y * a10.y + wv.z * a01.y + wv.w * a11.y;
            s1.x = wv.x * b00.x + wv.y * b10.x + wv.z * b01.x + wv.w * b11.x;
            s1.y = wv.x * b00.y + wv.y * b10.y + wv.z * b01.y + wv.w * b11.y;

            const __half2 h0 = __float22half2_rn(s0);
            const __half2 h1 = __float22half2_rn(s1);

            const int pp = k0 * 16 + warp;
            const uint32_t off = (uint32_t)pp * 256 + bswz((uint32_t)pp, (uint32_t)lane * 8);
            *(uint2*)(Anxt + off) =
                make_uint2(*(const uint32_t*)&h0, *(const uint32_t*)&h1);

            e = en;
            wv = wvn;
        }
    }
}

// ---------------------------------------------------------------------------
// Kernel 3: fused gather+mma, 512 threads / 16 warps, warp tile 32x64
// ---------------------------------------------------------------------------
__global__ __launch_bounds__(NTHREADS, 1)
void sphere_hmma_kernel(const float* __restrict__ bias,
                        float* __restrict__ out) {
    extern __shared__ char dsm[];
    const uint32_t raw = smem_u32(dsm);
    const uint32_t sb  = (raw + 1023u) & ~1023u;
    char* const smp = dsm + (sb - raw);

    const int tid  = threadIdx.x;
    const int lane = tid & 31;
    const int warp = tid >> 5;          // 0..15
    const int warp_m = warp >> 2;       // 0..3
    const int warp_n = warp & 3;        // 0..3
    const int tile = blockIdx.x;
    const int b    = tile >> 8;
    const int p0   = (tile & 255) * TILE_M;

    if (tid < 256) ((float*)(smp + SM_BIAS))[tid] = bias[tid];

    const uint2* __restrict__ xh2 =
        (const uint2*)(g_xh + (size_t)b * HW * CIN);

    float acc[2][8][4];
#pragma unroll
    for (int mi = 0; mi < 2; ++mi)
#pragma unroll
        for (int ni = 0; ni < 8; ++ni)
#pragma unroll
            for (int q = 0; q < 4; ++q) acc[mi][ni][q] = 0.0f;

    const uint32_t a_row_in_warp = (uint32_t)(lane & 15);
    const uint32_t a_koff        = (uint32_t)((lane >> 4) << 4);
    const uint32_t b_n_in_pair   = (uint32_t)(((lane >> 4) & 1) * 8 + (lane & 7));
    const uint32_t b_koff        = (uint32_t)(((lane >> 3) & 1) << 4);

    // ---- prologue: stage W(0); gather A(0) (table-driven, unfused) ----
    stageW_async(sb + SM_W0, g_Wf16, tid);
    cp_commit();
    {
        const int4*   __restrict__ tI = g_tabI + p0;
        const float4* __restrict__ tW = g_tabW + p0;
#pragma unroll 2
        for (int i = 0; i < 8; ++i) {
            const int pp = i * 16 + warp;
            const int4   e  = __ldg(tI + pp);
            const float4 wv = __ldg(tW + pp);
            const uint2 u00 = __ldg(xh2 + e.x + lane);
            const uint2 u10 = __ldg(xh2 + e.y + lane);
            const uint2 u01 = __ldg(xh2 + e.z + lane);
            const uint2 u11 = __ldg(xh2 + e.w + lane);
            const float2 a00 = __half22float2(*(const __half2*)&u00.x);
            const float2 b00 = __half22float2(*(const __half2*)&u00.y);
            const float2 a10 = __half22float2(*(const __half2*)&u10.x);
            const float2 b10 = __half22float2(*(const __half2*)&u10.y);
            const float2 a01 = __half22float2(*(const __half2*)&u01.x);
            const float2 b01 = __half22float2(*(const __half2*)&u01.y);
            const float2 a11 = __half22float2(*(const __half2*)&u11.x);
            const float2 b11 = __half22float2(*(const __half2*)&u11.y);
            float2 s0, s1;
            s0.x = wv.x * a00.x + wv.y * a10.x + wv.z * a01.x + wv.w * a11.x;
            s0.y = wv.x * a00.y + wv.y * a10.y + wv.z * a01.y + wv.w * a11.y;
            s1.x = wv.x * b00.x + wv.y * b10.x + wv.z * b01.x + wv.w * b11.x;
            s1.y = wv.x * b00.y + wv.y * b10.y + wv.z * b01.y + wv.w * b11.y;
            const __half2 h0 = __float22half2_rn(s0);
            const __half2 h1 = __float22half2_rn(s1);
            const uint32_t off = (uint32_t)pp * 256 + bswz((uint32_t)pp, (uint32_t)lane * 8);
            *(uint2*)(smp + SM_A0 + off) =
                make_uint2(*(const uint32_t*)&h0, *(const uint32_t*)&h1);
        }
    }
    cp_wait0();
    __syncthreads();

    for (int t = 0; t < 9; ++t) {
        const int cur = t & 1;
        const uint32_t Acur = sb + (cur ? SM_A1 : SM_A0);
        const uint32_t Wcur = sb + (cur ? SM_W1 : SM_W0);
        char* const Anxt = smp + (cur ? SM_A0 : SM_A1);
        const uint32_t Wnxt = sb + (cur ? SM_W0 : SM_W1);

        if (t < 8) {
            stageW_async(Wnxt, g_Wf16 + (size_t)(t + 1) * 65536, tid);
            cp_commit();
            mma_tap_fused<true>(Acur, Wcur, acc,
                                g_tabI + (t + 1) * HW + p0,
                                g_tabW + (t + 1) * HW + p0,
                                xh2, Anxt,
                                a_row_in_warp, a_koff, b_n_in_pair, b_koff,
                                warp_m, warp_n, lane, warp);
            cp_wait0();
        } else {
            mma_tap_fused<false>(Acur, Wcur, acc, nullptr, nullptr,
                                 xh2, nullptr,
                                 a_row_in_warp, a_koff, b_n_in_pair, b_koff,
                                 warp_m, warp_n, lane, warp);
        }
        __syncthreads();
    }

    // ---- epilogue: acc -> Dsm[co][px] -> coalesced out ----
    float* Dsm = (float*)smp;
    {
        const int rbase = warp_m * 32 + (lane >> 2);
        const int cbase = warp_n * 64 + 2 * (lane & 3);
#pragma unroll
        for (int mi = 0; mi < 2; ++mi) {
#pragma unroll
            for (int ni = 0; ni < 8; ++ni) {
                const int rr = rbase + mi * 16;
                const int cc = cbase + ni * 8;
                Dsm[(cc    ) * 128 + rr    ] = acc[mi][ni][0];
                Dsm[(cc + 1) * 128 + rr    ] = acc[mi][ni][1];
                Dsm[(cc    ) * 128 + rr + 8] = acc[mi][ni][2];
                Dsm[(cc + 1) * 128 + rr + 8] = acc[mi][ni][3];
            }
        }
    }
    __syncthreads();

    {
        const float* bs = (const float*)(smp + SM_BIAS);
        float* ob = out + (size_t)b * COUT * HW + p0;
#pragma unroll 4
        for (int it = 0; it < 16; ++it) {
            const int co = it * 16 + warp;
            const float bv = bs[co];
            float4 v = ((const float4*)(Dsm + co * 128))[lane];
            v.x += bv; v.y += bv; v.z += bv; v.w += bv;
            ((float4*)(ob + (size_t)co * HW))[lane] = v;
        }
    }
}

// ---------------------------------------------------------------------------
extern "C" void kernel_launch(void* const* d_in, const int* in_sizes, int n_in,
                              void* d_out, int out_size) {
    const float* x      = (const float*)d_in[0];   // (4,128,128,256)
    const float* weight = (const float*)d_in[1];   // (256,128,3,3)
    const float* bias   = (const float*)d_in[2];   // (256,)
    const float* grid   = (const float*)d_in[3];   // (1,384,768,2)
    float* out = (float*)d_out;                    // (4,256,128,256)

    cudaFuncSetAttribute(sphere_hmma_kernel,
                         cudaFuncAttributeMaxDynamicSharedMemorySize, SM_TOTAL);

    {
        dim3 g(HW / 32, CIN / 32, B_);
        dim3 blk(32, 8);
        transpose_x_kernel<<<g, blk>>>(x);
    }
    weight_prep_f16_kernel<<<(9 * 256 * 128 + 255) / 256, 256>>>(weight);
    grid_prep_kernel<<<(9 * HW + 255) / 256, 256>>>(grid);
    sphere_hmma_kernel<<<NTILES, NTHREADS, SM_TOTAL>>>(bias, out);
}